// round 9
// baseline (speedup 1.0000x reference)
#include <cuda_runtime.h>
#include <math.h>

// Problem constants
#define T_LEN 512
#define B_SZ  64
#define I_SZ  512
#define H_SZ  1024
#define G3H   3072
#define M_TOT 32768          // T*B

#define NBLK  128            // persistent blocks (1 per SM)
#define JT    8              // hidden units per block
#define NROW  24             // gate rows per block (3*JT)
#define NWARP 8
#define KSL   128            // k-slice per warp
#define CHKW  16             // k per warp-chunk
#define HSTW  20             // h window stride (floats)
#define REDS  66

typedef unsigned long long ull;

__device__ __align__(16) float g_gates[(size_t)M_TOT * G3H];
__device__ __align__(16) float g_h0[B_SZ * H_SZ];  // zero-init, never written
__device__ unsigned g_sync;

// ---------------------------------------------------------------------------
// f32x2 helpers
// ---------------------------------------------------------------------------
__device__ __forceinline__ ull dup2(float w) {
    ull r; asm("mov.b64 %0, {%1, %1};" : "=l"(r) : "f"(w)); return r;
}
__device__ __forceinline__ void ffma2(ull& d, ull a, ull b) {
    asm("fma.rn.f32x2 %0, %1, %2, %0;" : "+l"(d) : "l"(a), "l"(b));
}
__device__ __forceinline__ ull addx2(ull a, ull b) {
    ull r; asm("add.rn.f32x2 %0, %1, %2;" : "=l"(r) : "l"(a), "l"(b)); return r;
}
__device__ __forceinline__ float sum2(ull v) {
    float lo, hi;
    asm("mov.b64 {%0, %1}, %2;" : "=f"(lo), "=f"(hi) : "l"(v));
    return lo + hi;
}
__device__ __forceinline__ void unpack2(ull v, float& lo, float& hi) {
    asm("mov.b64 {%0, %1}, %2;" : "=f"(lo), "=f"(hi) : "l"(v));
}
__device__ __forceinline__ ull shflx16(ull v) {
    unsigned lo = (unsigned)v, hi = (unsigned)(v >> 32);
    lo = __shfl_xor_sync(0xffffffffu, lo, 16);
    hi = __shfl_xor_sync(0xffffffffu, hi, 16);
    return ((ull)hi << 32) | lo;
}

// ---------------------------------------------------------------------------
// Kernel A: x_gates = x @ w_ih^T + b_ih.  M=32768, N=3072, K=512.
// 128x128 tile, K-tile 8, 256 threads, thread tile 8m x 8n.
// ---------------------------------------------------------------------------
__global__ __launch_bounds__(256)
void gemm_xgates(const float* __restrict__ A,
                 const float* __restrict__ W,
                 const float* __restrict__ bias)
{
    __shared__ __align__(16) float As[2][8][132];
    __shared__ __align__(16) float Bs[2][8][132];

    const int m0 = blockIdx.y * 128;
    const int n0 = blockIdx.x * 128;
    const int tid = threadIdx.x;
    const int tm = tid >> 4;
    const int tn = tid & 15;
    const int lr = tid >> 1;
    const int lk4 = (tid & 1) * 4;

    ull acc[8][4];
    #pragma unroll
    for (int i = 0; i < 8; i++)
        #pragma unroll
        for (int p = 0; p < 4; p++) acc[i][p] = 0ull;

    float4 av = *(const float4*)&A[(size_t)(m0 + lr) * I_SZ + lk4];
    float4 wv = *(const float4*)&W[(size_t)(n0 + lr) * I_SZ + lk4];
    {
        As[0][lk4 + 0][lr] = av.x; As[0][lk4 + 1][lr] = av.y;
        As[0][lk4 + 2][lr] = av.z; As[0][lk4 + 3][lr] = av.w;
        Bs[0][lk4 + 0][lr] = wv.x; Bs[0][lk4 + 1][lr] = wv.y;
        Bs[0][lk4 + 2][lr] = wv.z; Bs[0][lk4 + 3][lr] = wv.w;
    }
    __syncthreads();

    #pragma unroll 1
    for (int kt = 0; kt < 64; kt++) {
        const int buf = kt & 1;
        if (kt < 63) {
            int k0 = (kt + 1) * 8 + lk4;
            av = *(const float4*)&A[(size_t)(m0 + lr) * I_SZ + k0];
            wv = *(const float4*)&W[(size_t)(n0 + lr) * I_SZ + k0];
        }
        #pragma unroll
        for (int kk = 0; kk < 8; kk++) {
            float4 a0 = *(const float4*)&As[buf][kk][tm * 8];
            float4 a1 = *(const float4*)&As[buf][kk][tm * 8 + 4];
            ull am[8];
            am[0] = dup2(a0.x); am[1] = dup2(a0.y);
            am[2] = dup2(a0.z); am[3] = dup2(a0.w);
            am[4] = dup2(a1.x); am[5] = dup2(a1.y);
            am[6] = dup2(a1.z); am[7] = dup2(a1.w);
            ulonglong2 b0 = *(const ulonglong2*)&Bs[buf][kk][tn * 8];
            ulonglong2 b1 = *(const ulonglong2*)&Bs[buf][kk][tn * 8 + 4];
            #pragma unroll
            for (int i = 0; i < 8; i++) {
                ffma2(acc[i][0], am[i], b0.x);
                ffma2(acc[i][1], am[i], b0.y);
                ffma2(acc[i][2], am[i], b1.x);
                ffma2(acc[i][3], am[i], b1.y);
            }
        }
        if (kt < 63) {
            const int nb = buf ^ 1;
            As[nb][lk4 + 0][lr] = av.x; As[nb][lk4 + 1][lr] = av.y;
            As[nb][lk4 + 2][lr] = av.z; As[nb][lk4 + 3][lr] = av.w;
            Bs[nb][lk4 + 0][lr] = wv.x; Bs[nb][lk4 + 1][lr] = wv.y;
            Bs[nb][lk4 + 2][lr] = wv.z; Bs[nb][lk4 + 3][lr] = wv.w;
        }
        __syncthreads();
    }

    const int nn = n0 + tn * 8;
    float4 bv0 = *(const float4*)&bias[nn];
    float4 bv1 = *(const float4*)&bias[nn + 4];
    #pragma unroll
    for (int i = 0; i < 8; i++) {
        float c0, c1, c2, c3, c4, c5, c6, c7;
        unpack2(acc[i][0], c0, c1);
        unpack2(acc[i][1], c2, c3);
        unpack2(acc[i][2], c4, c5);
        unpack2(acc[i][3], c6, c7);
        float4 o0 = make_float4(c0 + bv0.x, c1 + bv0.y, c2 + bv0.z, c3 + bv0.w);
        float4 o1 = make_float4(c4 + bv1.x, c5 + bv1.y, c6 + bv1.z, c7 + bv1.w);
        int row = m0 + tm * 8 + i;
        *(float4*)&g_gates[(size_t)row * G3H + nn]     = o0;
        *(float4*)&g_gates[(size_t)row * G3H + nn + 4] = o1;
    }
}

// ---------------------------------------------------------------------------
// Persistent GRU scan kernel.
// grid = 128 blocks (1/SM), 256 threads = 8 warps.
// Warp w: k-slice [w*128, w*128+128), ALL 24 gate rows.
// Lane (kh = lane>>4, bg = lane&15): k-half kh of each 16-k chunk,
// batches {bg, bg+16, bg+32, bg+48}.  acc[24 rows][4 batches] f32x2 (k-parity).
// Per chunk: W = 24 LDS.128 (2-addr), h = 8 per-lane LDS.128 -> fma-bound.
// K-half combine via shfl.xor 16 + add.f32x2.  Warp-private window: __syncwarp only.
// ---------------------------------------------------------------------------
__global__ void __launch_bounds__(256, 1)
gru_persistent(float* __restrict__ out,
               const float* __restrict__ w_hh,
               const float* __restrict__ b_hh)
{
    extern __shared__ __align__(16) float smem[];
    float* Ws  = smem;                           // [24][1024]      98304 B
    float* Hw  = Ws + NROW * H_SZ;               // [8][2][64][20]  81920 B
    float* Red = Hw + NWARP * 2 * 64 * HSTW;     // [8][24][66]     50688 B

    const int tid  = threadIdx.x;
    const int w    = tid >> 5;
    const int lane = tid & 31;
    const int kh   = lane >> 4;                  // k half within chunk
    const int bg   = lane & 15;                  // batch group
    const int j0   = blockIdx.x * JT;
    const int kofs = w * KSL;

    // ---- load W slice into smem (once); row = g*8 + jj ----
    for (int idx = tid; idx < NROW * (H_SZ / 4); idx += 256) {
        int row = idx >> 8;
        int q   = idx & 255;
        int g = row >> 3, jj = row & 7;
        *(float4*)&Ws[row * H_SZ + 4 * q] =
            *(const float4*)&w_hh[(size_t)(g * H_SZ + j0 + jj) * H_SZ + 4 * q];
    }

    // ---- epilogue mapping: outputs o = tid, tid+256 ----
    float bh[2][3];
    #pragma unroll
    for (int e = 0; e < 2; e++) {
        int o = tid + e * 256;
        int ej = j0 + (o & 7);
        bh[e][0] = b_hh[ej];
        bh[e][1] = b_hh[H_SZ + ej];
        bh[e][2] = b_hh[2 * H_SZ + ej];
    }

    float* HwW = Hw + w * (2 * 64 * HSTW);

    __syncthreads();

    unsigned target = NBLK;
    float* hn_out = out + (size_t)T_LEN * B_SZ * H_SZ;
    float hpv[2] = {0.f, 0.f};

    #pragma unroll 1
    for (int t = 0; t < T_LEN; t++) {
        const float* hp = (t == 0) ? g_h0
                        : out + (size_t)(t - 1) * B_SZ * H_SZ;
        float* ho = out + (size_t)t * B_SZ * H_SZ;

        // epilogue x-gate prefetch (hidden by mainloop)
        float xr[2], xz[2], xn[2];
        #pragma unroll
        for (int e = 0; e < 2; e++) {
            int o = tid + e * 256;
            const float* xg = g_gates + (size_t)t * B_SZ * G3H
                            + (size_t)(o >> 3) * G3H + j0 + (o & 7);
            xr[e] = __ldcg(&xg[0]);
            xz[e] = __ldcg(&xg[H_SZ]);
            xn[e] = __ldcg(&xg[2 * H_SZ]);
        }

        ull acc[NROW][4];
        #pragma unroll
        for (int r = 0; r < NROW; r++)
            #pragma unroll
            for (int j = 0; j < 4; j++) acc[r][j] = 0ull;

        // chunk 0: each lane loads batches {lane, lane+32} x 4 quads
        float4 r4[8];
        #pragma unroll
        for (int q = 0; q < 4; q++) {
            r4[q]     = __ldcg((const float4*)&hp[(size_t)lane * H_SZ + kofs + q * 4]);
            r4[4 + q] = __ldcg((const float4*)&hp[(size_t)(lane + 32) * H_SZ + kofs + q * 4]);
        }
        #pragma unroll
        for (int q = 0; q < 4; q++) {
            *(float4*)&HwW[lane * HSTW + q * 4]        = r4[q];
            *(float4*)&HwW[(lane + 32) * HSTW + q * 4] = r4[4 + q];
        }
        __syncwarp();

        #pragma unroll 1
        for (int c = 0; c < 8; c++) {
            const int buf = c & 1;
            if (c < 7) {
                int kc = kofs + (c + 1) * CHKW;
                #pragma unroll
                for (int q = 0; q < 4; q++) {
                    r4[q]     = __ldcg((const float4*)&hp[(size_t)lane * H_SZ + kc + q * 4]);
                    r4[4 + q] = __ldcg((const float4*)&hp[(size_t)(lane + 32) * H_SZ + kc + q * 4]);
                }
            }
            const float* hb = &HwW[buf * 64 * HSTW + kh * 8];
            const float* wb = &Ws[kofs + c * CHKW + kh * 8];
            #pragma unroll
            for (int u = 0; u < 2; u++) {
                ulonglong2 hv[4];
                #pragma unroll
                for (int j = 0; j < 4; j++)
                    hv[j] = *(const ulonglong2*)&hb[(bg + 16 * j) * HSTW + u * 4];
                #pragma unroll
                for (int r = 0; r < NROW; r++) {
                    ulonglong2 wv = *(const ulonglong2*)&wb[r * H_SZ + u * 4];
                    #pragma unroll
                    for (int j = 0; j < 4; j++) {
                        ffma2(acc[r][j], hv[j].x, wv.x);
                        ffma2(acc[r][j], hv[j].y, wv.y);
                    }
                }
            }
            if (c < 7) {
                const int nb = buf ^ 1;
                #pragma unroll
                for (int q = 0; q < 4; q++) {
                    *(float4*)&HwW[(nb * 64 + lane) * HSTW + q * 4]      = r4[q];
                    *(float4*)&HwW[(nb * 64 + lane + 32) * HSTW + q * 4] = r4[4 + q];
                }
            }
            __syncwarp();
        }

        // ---- k-half combine (shfl.xor 16) + store partials to Red ----
        // After combine every lane holds full k-slice sums for its 4 batches.
        // kh==0 lanes store rows 0..11, kh==1 lanes store rows 12..23.
        #pragma unroll
        for (int r = 0; r < NROW; r++) {
            #pragma unroll
            for (int j = 0; j < 4; j++) {
                ull v = addx2(acc[r][j], shflx16(acc[r][j]));
                acc[r][j] = v;
            }
        }
        {
            const int rb = kh * 12;
            #pragma unroll
            for (int rr = 0; rr < 12; rr++) {
                float* R = Red + (size_t)(w * NROW + rb + rr) * REDS;
                #pragma unroll
                for (int j = 0; j < 4; j++)
                    R[bg + 16 * j] = sum2(acc[rb + rr][j]);
            }
        }
        __syncthreads();

        // ---- fused gate epilogue: 2 outputs per thread ----
        #pragma unroll
        for (int e = 0; e < 2; e++) {
            int o   = tid + e * 256;
            int eb  = o >> 3;
            int ejj = o & 7;
            float sr = 0.f, sz = 0.f, sn = 0.f;
            #pragma unroll
            for (int s = 0; s < NWARP; s++) {
                const float* R = Red + (size_t)s * NROW * REDS;
                sr += R[(0 * 8 + ejj) * REDS + eb];
                sz += R[(1 * 8 + ejj) * REDS + eb];
                sn += R[(2 * 8 + ejj) * REDS + eb];
            }
            float r = 1.f / (1.f + expf(-(xr[e] + sr + bh[e][0])));
            float z = 1.f / (1.f + expf(-(xz[e] + sz + bh[e][1])));
            float n = tanhf(xn[e] + r * (sn + bh[e][2]));
            float hnew = (1.f - z) * n + z * hpv[e];
            __stcg(&ho[(size_t)eb * H_SZ + j0 + ejj], hnew);
            if (t == T_LEN - 1)
                __stcg(&hn_out[(size_t)eb * H_SZ + j0 + ejj], hnew);
            hpv[e] = hnew;
        }

        // ---- grid-wide sync ----
        __threadfence();
        __syncthreads();
        if (tid == 0) {
            asm volatile("red.release.gpu.global.add.u32 [%0], %1;"
                         :: "l"(&g_sync), "r"(1u) : "memory");
            unsigned v;
            do {
                asm volatile("ld.acquire.gpu.global.u32 %0, [%1];"
                             : "=r"(v) : "l"(&g_sync) : "memory");
            } while (v < target);
        }
        __syncthreads();
        target += NBLK;
    }
}

extern "C" void kernel_launch(void* const* d_in, const int* in_sizes, int n_in,
                              void* d_out, int out_size)
{
    const float* x    = (const float*)d_in[0];   // (T, B, I)
    const float* w_ih = (const float*)d_in[1];   // (3H, I)
    const float* w_hh = (const float*)d_in[2];   // (3H, H)
    const float* b_ih = (const float*)d_in[3];   // (3H,)
    const float* b_hh = (const float*)d_in[4];   // (3H,)
    float* out = (float*)d_out;

    // reset the grid-sync counter (graph-capturable H2D memcpy)
    static unsigned h_zero = 0;
    void* sync_addr = nullptr;
    cudaGetSymbolAddress(&sync_addr, g_sync);
    cudaMemcpyAsync(sync_addr, &h_zero, sizeof(unsigned),
                    cudaMemcpyHostToDevice, 0);

    // Phase 1: input projection GEMM
    dim3 gridA(G3H / 128, M_TOT / 128);
    gemm_xgates<<<gridA, 256>>>(x, w_ih, b_ih);

    // Phase 2: persistent recurrent scan (all 512 steps in one kernel)
    const int smem_bytes = (NROW * H_SZ + NWARP * 2 * 64 * HSTW
                            + NWARP * NROW * REDS) * (int)sizeof(float);
    cudaFuncSetAttribute(gru_persistent,
                         cudaFuncAttributeMaxDynamicSharedMemorySize, smem_bytes);
    gru_persistent<<<NBLK, 256, smem_bytes>>>(out, w_hh, b_hh);
}

// round 10
// speedup vs baseline: 3.4466x; 3.4466x over previous
#include <cuda_runtime.h>
#include <math.h>

// Problem constants
#define T_LEN 512
#define B_SZ  64
#define I_SZ  512
#define H_SZ  1024
#define G3H   3072
#define M_TOT 32768          // T*B

#define NBLK  128            // persistent blocks (1 per SM)
#define JT    8              // hidden units per block
#define NROW  24             // gate rows per block (3*JT)
#define NWARP 8
#define WST   1032           // h window row stride (floats)
#define REDS  68

typedef unsigned long long ull;

__device__ __align__(16) float g_gates[(size_t)M_TOT * G3H];
__device__ __align__(16) float g_h0[B_SZ * H_SZ];  // zero-init, never written
__device__ unsigned g_sync;

// ---------------------------------------------------------------------------
// f32x2 helpers
// ---------------------------------------------------------------------------
__device__ __forceinline__ ull pack2(float lo, float hi) {
    ull r; asm("mov.b64 %0, {%1, %2};" : "=l"(r) : "f"(lo), "f"(hi)); return r;
}
__device__ __forceinline__ ull dup2(float w) {
    ull r; asm("mov.b64 %0, {%1, %1};" : "=l"(r) : "f"(w)); return r;
}
__device__ __forceinline__ void ffma2(ull& d, ull a, ull b) {
    asm("fma.rn.f32x2 %0, %1, %2, %0;" : "+l"(d) : "l"(a), "l"(b));
}
__device__ __forceinline__ ull addx2(ull a, ull b) {
    ull r; asm("add.rn.f32x2 %0, %1, %2;" : "=l"(r) : "l"(a), "l"(b)); return r;
}
__device__ __forceinline__ float sum2(ull v) {
    float lo, hi;
    asm("mov.b64 {%0, %1}, %2;" : "=f"(lo), "=f"(hi) : "l"(v));
    return lo + hi;
}
__device__ __forceinline__ void unpack2(ull v, float& lo, float& hi) {
    asm("mov.b64 {%0, %1}, %2;" : "=f"(lo), "=f"(hi) : "l"(v));
}
__device__ __forceinline__ ull shflxor2(ull v, int m) {
    unsigned lo = (unsigned)v, hi = (unsigned)(v >> 32);
    lo = __shfl_xor_sync(0xffffffffu, lo, m);
    hi = __shfl_xor_sync(0xffffffffu, hi, m);
    return ((ull)hi << 32) | lo;
}

// ---------------------------------------------------------------------------
// Kernel A: x_gates = x @ w_ih^T + b_ih.  M=32768, N=3072, K=512.
// (unchanged from best-known version)
// ---------------------------------------------------------------------------
__global__ __launch_bounds__(256)
void gemm_xgates(const float* __restrict__ A,
                 const float* __restrict__ W,
                 const float* __restrict__ bias)
{
    __shared__ __align__(16) float As[2][8][132];
    __shared__ __align__(16) float Bs[2][8][132];

    const int m0 = blockIdx.y * 128;
    const int n0 = blockIdx.x * 128;
    const int tid = threadIdx.x;
    const int tm = tid >> 4;
    const int tn = tid & 15;
    const int lr = tid >> 1;
    const int lk4 = (tid & 1) * 4;

    ull acc[8][4];
    #pragma unroll
    for (int i = 0; i < 8; i++)
        #pragma unroll
        for (int p = 0; p < 4; p++) acc[i][p] = 0ull;

    float4 av = *(const float4*)&A[(size_t)(m0 + lr) * I_SZ + lk4];
    float4 wv = *(const float4*)&W[(size_t)(n0 + lr) * I_SZ + lk4];
    {
        As[0][lk4 + 0][lr] = av.x; As[0][lk4 + 1][lr] = av.y;
        As[0][lk4 + 2][lr] = av.z; As[0][lk4 + 3][lr] = av.w;
        Bs[0][lk4 + 0][lr] = wv.x; Bs[0][lk4 + 1][lr] = wv.y;
        Bs[0][lk4 + 2][lr] = wv.z; Bs[0][lk4 + 3][lr] = wv.w;
    }
    __syncthreads();

    #pragma unroll 1
    for (int kt = 0; kt < 64; kt++) {
        const int buf = kt & 1;
        if (kt < 63) {
            int k0 = (kt + 1) * 8 + lk4;
            av = *(const float4*)&A[(size_t)(m0 + lr) * I_SZ + k0];
            wv = *(const float4*)&W[(size_t)(n0 + lr) * I_SZ + k0];
        }
        #pragma unroll
        for (int kk = 0; kk < 8; kk++) {
            float4 a0 = *(const float4*)&As[buf][kk][tm * 8];
            float4 a1 = *(const float4*)&As[buf][kk][tm * 8 + 4];
            ull am[8];
            am[0] = dup2(a0.x); am[1] = dup2(a0.y);
            am[2] = dup2(a0.z); am[3] = dup2(a0.w);
            am[4] = dup2(a1.x); am[5] = dup2(a1.y);
            am[6] = dup2(a1.z); am[7] = dup2(a1.w);
            ulonglong2 b0 = *(const ulonglong2*)&Bs[buf][kk][tn * 8];
            ulonglong2 b1 = *(const ulonglong2*)&Bs[buf][kk][tn * 8 + 4];
            #pragma unroll
            for (int i = 0; i < 8; i++) {
                ffma2(acc[i][0], am[i], b0.x);
                ffma2(acc[i][1], am[i], b0.y);
                ffma2(acc[i][2], am[i], b1.x);
                ffma2(acc[i][3], am[i], b1.y);
            }
        }
        if (kt < 63) {
            const int nb = buf ^ 1;
            As[nb][lk4 + 0][lr] = av.x; As[nb][lk4 + 1][lr] = av.y;
            As[nb][lk4 + 2][lr] = av.z; As[nb][lk4 + 3][lr] = av.w;
            Bs[nb][lk4 + 0][lr] = wv.x; Bs[nb][lk4 + 1][lr] = wv.y;
            Bs[nb][lk4 + 2][lr] = wv.z; Bs[nb][lk4 + 3][lr] = wv.w;
        }
        __syncthreads();
    }

    const int nn = n0 + tn * 8;
    float4 bv0 = *(const float4*)&bias[nn];
    float4 bv1 = *(const float4*)&bias[nn + 4];
    #pragma unroll
    for (int i = 0; i < 8; i++) {
        float c0, c1, c2, c3, c4, c5, c6, c7;
        unpack2(acc[i][0], c0, c1);
        unpack2(acc[i][1], c2, c3);
        unpack2(acc[i][2], c4, c5);
        unpack2(acc[i][3], c6, c7);
        float4 o0 = make_float4(c0 + bv0.x, c1 + bv0.y, c2 + bv0.z, c3 + bv0.w);
        float4 o1 = make_float4(c4 + bv1.x, c5 + bv1.y, c6 + bv1.z, c7 + bv1.w);
        int row = m0 + tm * 8 + i;
        *(float4*)&g_gates[(size_t)row * G3H + nn]     = o0;
        *(float4*)&g_gates[(size_t)row * G3H + nn + 4] = o1;
    }
}

// ---------------------------------------------------------------------------
// Persistent GRU scan — W-stationary in registers.
// 128 blocks, 256 threads, 8 warps.  Warp w: k-slice [w*128, +128), 24 rows.
// Lane (rg = lane&7 -> 3 rows, ks2 = lane>>3 -> 32-k sub-slice).
// W regs: 48 ull/lane.  acc[3 rows][4 batches] per tile; shfl.xor(8,16) k-reduce.
// h window: double-buffered 16-batch quarters, staged by cp.async into a
// ks2-interleaved layout so the h LDS.128 is a 64B/1-wavefront access.
// ---------------------------------------------------------------------------
__global__ void __launch_bounds__(256, 1)
gru_persistent(float* __restrict__ out,
               const float* __restrict__ w_hh,
               const float* __restrict__ b_hh)
{
    extern __shared__ __align__(16) float smem[];
    float* Hh  = smem;                           // [2 buf][16 b][WST]
    float* Red = Hh + 2 * 16 * WST;              // [8 w][24][REDS]

    const int tid  = threadIdx.x;
    const int w    = tid >> 5;
    const int lane = tid & 31;
    const int rg   = lane & 7;                   // 3 rows each
    const int ks2  = lane >> 3;                  // 32-k sub-slice
    const int j0   = blockIdx.x * JT;
    const int kofs = w * 128;

    // ---- W stationary load (once): Wreg[r][16 k-pairs] ----
    ull Wreg[3][16];
    #pragma unroll
    for (int r = 0; r < 3; r++) {
        int row = rg * 3 + r;
        int g = row >> 3, jj = row & 7;
        const float* src = &w_hh[(size_t)(g * H_SZ + j0 + jj) * H_SZ
                                 + kofs + ks2 * 32];
        #pragma unroll
        for (int q = 0; q < 8; q++) {
            float4 f = *(const float4*)&src[4 * q];
            Wreg[r][2 * q]     = pack2(f.x, f.y);
            Wreg[r][2 * q + 1] = pack2(f.z, f.w);
        }
    }

    // ---- epilogue mapping: outputs o = tid, tid+256 ----
    float bh[2][3];
    #pragma unroll
    for (int e = 0; e < 2; e++) {
        int o = tid + e * 256;
        int ej = j0 + (o & 7);
        bh[e][0] = b_hh[ej];
        bh[e][1] = b_hh[H_SZ + ej];
        bh[e][2] = b_hh[2 * H_SZ + ej];
    }

    // ---- stage mapping: thread stages 16 float4 of one batch row ----
    const int sb   = tid >> 4;                   // batch row in quarter (0..15)
    const int sseg = tid & 15;                   // 64-float k segment
    unsigned hh_u32;
    {
        void* p = (void*)Hh;
        hh_u32 = (unsigned)__cvta_generic_to_shared(p);
    }

    __syncthreads();

    unsigned target = NBLK;
    float* hn_out = out + (size_t)T_LEN * B_SZ * H_SZ;
    float hpv[2] = {0.f, 0.f};

    #pragma unroll 1
    for (int t = 0; t < T_LEN; t++) {
        const float* hp = (t == 0) ? g_h0
                        : out + (size_t)(t - 1) * B_SZ * H_SZ;
        float* ho = out + (size_t)t * B_SZ * H_SZ;

        // epilogue x-gate prefetch
        float xr[2], xz[2], xn[2];
        #pragma unroll
        for (int e = 0; e < 2; e++) {
            int o = tid + e * 256;
            const float* xg = g_gates + (size_t)t * B_SZ * G3H
                            + (size_t)(o >> 3) * G3H + j0 + (o & 7);
            xr[e] = __ldcg(&xg[0]);
            xz[e] = __ldcg(&xg[H_SZ]);
            xn[e] = __ldcg(&xg[2 * H_SZ]);
        }

        // ---- stage quarter 0 into buf 0 (cp.async, permuted layout) ----
        {
            const float* srow = hp + (size_t)sb * H_SZ + sseg * 64;
            unsigned drow = hh_u32 + (unsigned)(sb * WST) * 4u
                          + (unsigned)((sseg >> 1) * 32 + (sseg & 1) * 2) * 16u;
            #pragma unroll
            for (int j = 0; j < 16; j++) {
                unsigned dst = drow + (unsigned)(((j & 7) * 4 + (j >> 3)) * 16);
                asm volatile("cp.async.cg.shared.global [%0], [%1], 16;"
                             :: "r"(dst), "l"(srow + 4 * j) : "memory");
            }
            asm volatile("cp.async.commit_group;" ::: "memory");
            asm volatile("cp.async.wait_group 0;" ::: "memory");
        }
        __syncthreads();

        // ---- quarters ----
        #pragma unroll 1
        for (int q = 0; q < 4; q++) {
            const int buf = q & 1;
            // fire staging for next quarter (overlaps compute)
            if (q < 3) {
                const float* srow = hp + (size_t)((q + 1) * 16 + sb) * H_SZ + sseg * 64;
                unsigned drow = hh_u32 + (unsigned)((buf ^ 1) * 16 * WST + sb * WST) * 4u
                              + (unsigned)((sseg >> 1) * 32 + (sseg & 1) * 2) * 16u;
                #pragma unroll
                for (int j = 0; j < 16; j++) {
                    unsigned dst = drow + (unsigned)(((j & 7) * 4 + (j >> 3)) * 16);
                    asm volatile("cp.async.cg.shared.global [%0], [%1], 16;"
                                 :: "r"(dst), "l"(srow + 4 * j) : "memory");
                }
                asm volatile("cp.async.commit_group;" ::: "memory");
            }

            // 4 tiles of 4 batches
            const float* hq = &Hh[buf * 16 * WST + w * 128 + ks2 * 4];
            #pragma unroll 1
            for (int bt = 0; bt < 4; bt++) {
                ull acc[3][4];
                #pragma unroll
                for (int r = 0; r < 3; r++)
                    #pragma unroll
                    for (int b = 0; b < 4; b++) acc[r][b] = 0ull;

                const float* hb0 = hq + (bt * 4) * WST;
                #pragma unroll
                for (int v = 0; v < 4; v++) {
                    ulonglong2 ha[4], hb2[4];
                    #pragma unroll
                    for (int b = 0; b < 4; b++) {
                        ha[b]  = *(const ulonglong2*)&hb0[b * WST + 32 * v];
                        hb2[b] = *(const ulonglong2*)&hb0[b * WST + 32 * v + 16];
                    }
                    #pragma unroll
                    for (int r = 0; r < 3; r++) {
                        ull w0 = Wreg[r][4 * v + 0];
                        ull w1 = Wreg[r][4 * v + 1];
                        ull w2 = Wreg[r][4 * v + 2];
                        ull w3 = Wreg[r][4 * v + 3];
                        #pragma unroll
                        for (int b = 0; b < 4; b++) {
                            ffma2(acc[r][b], w0, ha[b].x);
                            ffma2(acc[r][b], w1, ha[b].y);
                            ffma2(acc[r][b], w2, hb2[b].x);
                            ffma2(acc[r][b], w3, hb2[b].y);
                        }
                    }
                }

                // k-reduce over ks2 (lanes xor 8, 16), lanes 0..7 write Red
                #pragma unroll
                for (int r = 0; r < 3; r++) {
                    #pragma unroll
                    for (int b = 0; b < 4; b++) {
                        ull v2 = addx2(acc[r][b], shflxor2(acc[r][b], 8));
                        v2 = addx2(v2, shflxor2(v2, 16));
                        if (lane < 8) {
                            Red[(size_t)(w * NROW + rg * 3 + r) * REDS
                                + q * 16 + bt * 4 + b] = sum2(v2);
                        }
                    }
                }
            }

            if (q < 3)
                asm volatile("cp.async.wait_group 0;" ::: "memory");
            __syncthreads();
        }

        // ---- fused gate epilogue: 2 outputs per thread ----
        #pragma unroll
        for (int e = 0; e < 2; e++) {
            int o   = tid + e * 256;
            int eb  = o >> 3;
            int ejj = o & 7;
            float sr = 0.f, sz = 0.f, sn = 0.f;
            #pragma unroll
            for (int s = 0; s < NWARP; s++) {
                const float* R = Red + (size_t)s * NROW * REDS;
                sr += R[(0 * 8 + ejj) * REDS + eb];
                sz += R[(1 * 8 + ejj) * REDS + eb];
                sn += R[(2 * 8 + ejj) * REDS + eb];
            }
            float r = 1.f / (1.f + expf(-(xr[e] + sr + bh[e][0])));
            float z = 1.f / (1.f + expf(-(xz[e] + sz + bh[e][1])));
            float n = tanhf(xn[e] + r * (sn + bh[e][2]));
            float hnew = (1.f - z) * n + z * hpv[e];
            __stcg(&ho[(size_t)eb * H_SZ + j0 + ejj], hnew);
            if (t == T_LEN - 1)
                __stcg(&hn_out[(size_t)eb * H_SZ + j0 + ejj], hnew);
            hpv[e] = hnew;
        }

        // ---- grid-wide sync ----
        __threadfence();
        __syncthreads();
        if (tid == 0) {
            asm volatile("red.release.gpu.global.add.u32 [%0], %1;"
                         :: "l"(&g_sync), "r"(1u) : "memory");
            unsigned v;
            do {
                asm volatile("ld.acquire.gpu.global.u32 %0, [%1];"
                             : "=r"(v) : "l"(&g_sync) : "memory");
            } while (v < target);
        }
        __syncthreads();
        target += NBLK;
    }
}

extern "C" void kernel_launch(void* const* d_in, const int* in_sizes, int n_in,
                              void* d_out, int out_size)
{
    const float* x    = (const float*)d_in[0];   // (T, B, I)
    const float* w_ih = (const float*)d_in[1];   // (3H, I)
    const float* w_hh = (const float*)d_in[2];   // (3H, H)
    const float* b_ih = (const float*)d_in[3];   // (3H,)
    const float* b_hh = (const float*)d_in[4];   // (3H,)
    float* out = (float*)d_out;

    // reset the grid-sync counter (graph-capturable H2D memcpy)
    static unsigned h_zero = 0;
    void* sync_addr = nullptr;
    cudaGetSymbolAddress(&sync_addr, g_sync);
    cudaMemcpyAsync(sync_addr, &h_zero, sizeof(unsigned),
                    cudaMemcpyHostToDevice, 0);

    // Phase 1: input projection GEMM
    dim3 gridA(G3H / 128, M_TOT / 128);
    gemm_xgates<<<gridA, 256>>>(x, w_ih, b_ih);

    // Phase 2: persistent recurrent scan
    const int smem_bytes = (2 * 16 * WST + NWARP * NROW * REDS)
                           * (int)sizeof(float);
    cudaFuncSetAttribute(gru_persistent,
                         cudaFuncAttributeMaxDynamicSharedMemorySize, smem_bytes);
    gru_persistent<<<NBLK, 256, smem_bytes>>>(out, w_hh, b_hh);
}

// round 11
// speedup vs baseline: 4.8676x; 1.4123x over previous
#include <cuda_runtime.h>
#include <math.h>

// Problem constants
#define T_LEN 512
#define B_SZ  64
#define I_SZ  512
#define H_SZ  1024
#define G3H   3072
#define M_TOT 32768          // T*B

#define NBLK  128            // persistent blocks (1 per SM)
#define JT    8              // hidden units per block
#define NROW  24             // gate rows per block (3*JT)
#define NWARP 8
#define KSL   128            // k-slice per warp
#define CHK   16             // k per chunk
#define HST   20             // h window stride (floats; 80B, 16B-aligned)
#define REDS  66

typedef unsigned long long ull;

__device__ __align__(16) float g_gates[(size_t)M_TOT * G3H];
__device__ __align__(16) float g_h0[B_SZ * H_SZ];  // zero-init, never written
__device__ unsigned g_sync;

// ---------------------------------------------------------------------------
// f32x2 helpers
// ---------------------------------------------------------------------------
__device__ __forceinline__ ull dup2(float w) {
    ull r; asm("mov.b64 %0, {%1, %1};" : "=l"(r) : "f"(w)); return r;
}
__device__ __forceinline__ void ffma2(ull& d, ull a, ull b) {
    asm("fma.rn.f32x2 %0, %1, %2, %0;" : "+l"(d) : "l"(a), "l"(b));
}
__device__ __forceinline__ float sum2(ull v) {
    float lo, hi;
    asm("mov.b64 {%0, %1}, %2;" : "=f"(lo), "=f"(hi) : "l"(v));
    return lo + hi;
}
__device__ __forceinline__ void unpack2(ull v, float& lo, float& hi) {
    asm("mov.b64 {%0, %1}, %2;" : "=f"(lo), "=f"(hi) : "l"(v));
}

// ---------------------------------------------------------------------------
// Kernel A: x_gates = x @ w_ih^T + b_ih.  M=32768, N=3072, K=512.
// 128x128 tile, K-tile 8, 256 threads, thread tile 8m x 8n.  (best known)
// ---------------------------------------------------------------------------
__global__ __launch_bounds__(256)
void gemm_xgates(const float* __restrict__ A,
                 const float* __restrict__ W,
                 const float* __restrict__ bias)
{
    __shared__ __align__(16) float As[2][8][132];
    __shared__ __align__(16) float Bs[2][8][132];

    const int m0 = blockIdx.y * 128;
    const int n0 = blockIdx.x * 128;
    const int tid = threadIdx.x;
    const int tm = tid >> 4;
    const int tn = tid & 15;
    const int lr = tid >> 1;
    const int lk4 = (tid & 1) * 4;

    ull acc[8][4];
    #pragma unroll
    for (int i = 0; i < 8; i++)
        #pragma unroll
        for (int p = 0; p < 4; p++) acc[i][p] = 0ull;

    float4 av = *(const float4*)&A[(size_t)(m0 + lr) * I_SZ + lk4];
    float4 wv = *(const float4*)&W[(size_t)(n0 + lr) * I_SZ + lk4];
    {
        As[0][lk4 + 0][lr] = av.x; As[0][lk4 + 1][lr] = av.y;
        As[0][lk4 + 2][lr] = av.z; As[0][lk4 + 3][lr] = av.w;
        Bs[0][lk4 + 0][lr] = wv.x; Bs[0][lk4 + 1][lr] = wv.y;
        Bs[0][lk4 + 2][lr] = wv.z; Bs[0][lk4 + 3][lr] = wv.w;
    }
    __syncthreads();

    #pragma unroll 1
    for (int kt = 0; kt < 64; kt++) {
        const int buf = kt & 1;
        if (kt < 63) {
            int k0 = (kt + 1) * 8 + lk4;
            av = *(const float4*)&A[(size_t)(m0 + lr) * I_SZ + k0];
            wv = *(const float4*)&W[(size_t)(n0 + lr) * I_SZ + k0];
        }
        #pragma unroll
        for (int kk = 0; kk < 8; kk++) {
            float4 a0 = *(const float4*)&As[buf][kk][tm * 8];
            float4 a1 = *(const float4*)&As[buf][kk][tm * 8 + 4];
            ull am[8];
            am[0] = dup2(a0.x); am[1] = dup2(a0.y);
            am[2] = dup2(a0.z); am[3] = dup2(a0.w);
            am[4] = dup2(a1.x); am[5] = dup2(a1.y);
            am[6] = dup2(a1.z); am[7] = dup2(a1.w);
            ulonglong2 b0 = *(const ulonglong2*)&Bs[buf][kk][tn * 8];
            ulonglong2 b1 = *(const ulonglong2*)&Bs[buf][kk][tn * 8 + 4];
            #pragma unroll
            for (int i = 0; i < 8; i++) {
                ffma2(acc[i][0], am[i], b0.x);
                ffma2(acc[i][1], am[i], b0.y);
                ffma2(acc[i][2], am[i], b1.x);
                ffma2(acc[i][3], am[i], b1.y);
            }
        }
        if (kt < 63) {
            const int nb = buf ^ 1;
            As[nb][lk4 + 0][lr] = av.x; As[nb][lk4 + 1][lr] = av.y;
            As[nb][lk4 + 2][lr] = av.z; As[nb][lk4 + 3][lr] = av.w;
            Bs[nb][lk4 + 0][lr] = wv.x; Bs[nb][lk4 + 1][lr] = wv.y;
            Bs[nb][lk4 + 2][lr] = wv.z; Bs[nb][lk4 + 3][lr] = wv.w;
        }
        __syncthreads();
    }

    const int nn = n0 + tn * 8;
    float4 bv0 = *(const float4*)&bias[nn];
    float4 bv1 = *(const float4*)&bias[nn + 4];
    #pragma unroll
    for (int i = 0; i < 8; i++) {
        float c0, c1, c2, c3, c4, c5, c6, c7;
        unpack2(acc[i][0], c0, c1);
        unpack2(acc[i][1], c2, c3);
        unpack2(acc[i][2], c4, c5);
        unpack2(acc[i][3], c6, c7);
        float4 o0 = make_float4(c0 + bv0.x, c1 + bv0.y, c2 + bv0.z, c3 + bv0.w);
        float4 o1 = make_float4(c4 + bv1.x, c5 + bv1.y, c6 + bv1.z, c7 + bv1.w);
        int row = m0 + tm * 8 + i;
        *(float4*)&g_gates[(size_t)row * G3H + nn]     = o0;
        *(float4*)&g_gates[(size_t)row * G3H + nn + 4] = o1;
    }
}

// ---------------------------------------------------------------------------
// Persistent GRU scan kernel — round-7 structure + cp.async staging.
// grid = 128 blocks (1/SM), 256 threads = 8 warps.
// Warp w owns k-slice [w*128, w*128+128) and ALL 24 gate rows.
// W slice resident in smem (96KB), broadcast LDS.128.
// h window double-buffered, staged by cp.async (issue-ahead-1, warp-private).
// Lane l: batches l and l+32; 48 f32x2 accumulators (24 rows x 2 batches).
// ---------------------------------------------------------------------------
__global__ void __launch_bounds__(256, 1)
gru_persistent(float* __restrict__ out,
               const float* __restrict__ w_hh,
               const float* __restrict__ b_hh)
{
    extern __shared__ __align__(16) float smem[];
    float* Ws  = smem;                           // [24][1024]      98304 B
    float* Hw  = Ws + NROW * H_SZ;               // [8 w][2][64][HST] 81920 B
    float* Red = Hw + NWARP * 2 * 64 * HST;      // [8 w][24][REDS]  50688 B

    const int tid  = threadIdx.x;
    const int w    = tid >> 5;
    const int lane = tid & 31;
    const int j0   = blockIdx.x * JT;
    const int kofs = w * KSL;

    // ---- load W slice into smem (once); row = g*8 + jj ----
    for (int idx = tid; idx < NROW * (H_SZ / 4); idx += 256) {
        int row = idx >> 8;
        int q   = idx & 255;
        int g = row >> 3, jj = row & 7;
        *(float4*)&Ws[row * H_SZ + 4 * q] =
            *(const float4*)&w_hh[(size_t)(g * H_SZ + j0 + jj) * H_SZ + 4 * q];
    }

    // ---- epilogue mapping: outputs o = tid, tid+256 ----
    float bh[2][3];
    #pragma unroll
    for (int e = 0; e < 2; e++) {
        int o = tid + e * 256;
        int ej = j0 + (o & 7);
        bh[e][0] = b_hh[ej];
        bh[e][1] = b_hh[H_SZ + ej];
        bh[e][2] = b_hh[2 * H_SZ + ej];
    }

    // ---- loader mapping: lane -> 8 batches (lb + 8i), k-quad lq ----
    const int lb = lane >> 2;                   // 0..7
    const int lq = lane & 3;                    // 0..3
    float* HwW = Hw + w * (2 * 64 * HST);
    // smem byte addresses for cp.async destinations (per buffer)
    unsigned hw_smem = (unsigned)__cvta_generic_to_shared((void*)HwW);
    const unsigned dst_lane_off = (unsigned)(lq * 16);   // lq*4 floats

    __syncthreads();

    unsigned target = NBLK;
    float* hn_out = out + (size_t)T_LEN * B_SZ * H_SZ;
    float hpv[2] = {0.f, 0.f};

    #pragma unroll 1
    for (int t = 0; t < T_LEN; t++) {
        const float* hp = (t == 0) ? g_h0
                        : out + (size_t)(t - 1) * B_SZ * H_SZ;
        float* ho = out + (size_t)t * B_SZ * H_SZ;

        // epilogue x-gate prefetch (hidden by mainloop)
        float xr[2], xz[2], xn[2];
        #pragma unroll
        for (int e = 0; e < 2; e++) {
            int o = tid + e * 256;
            const float* xg = g_gates + (size_t)t * B_SZ * G3H
                            + (size_t)(o >> 3) * G3H + j0 + (o & 7);
            xr[e] = __ldcg(&xg[0]);
            xz[e] = __ldcg(&xg[H_SZ]);
            xn[e] = __ldcg(&xg[2 * H_SZ]);
        }

        ull acc[NROW][2];
        #pragma unroll
        for (int i = 0; i < NROW; i++) { acc[i][0] = 0ull; acc[i][1] = 0ull; }

        // stage chunk 0 into buf 0 (cp.async)
        {
            const float* src0 = hp + (size_t)lb * H_SZ + kofs + lq * 4;
            unsigned dst0 = hw_smem + (unsigned)(lb * HST) * 4u + dst_lane_off;
            #pragma unroll
            for (int i = 0; i < 8; i++) {
                asm volatile("cp.async.cg.shared.global [%0], [%1], 16;"
                             :: "r"(dst0 + (unsigned)(8 * i * HST) * 4u),
                                "l"(src0 + (size_t)(8 * i) * H_SZ) : "memory");
            }
            asm volatile("cp.async.commit_group;" ::: "memory");
        }

        #pragma unroll 1
        for (int c = 0; c < 8; c++) {
            const int buf = c & 1;
            // all lanes done reading buf^1 (chunk c-1) before overwriting it
            __syncwarp();
            if (c < 7) {
                const int kc = kofs + (c + 1) * CHK;
                const float* srcN = hp + (size_t)lb * H_SZ + kc + lq * 4;
                unsigned dstN = hw_smem
                              + (unsigned)(((buf ^ 1) * 64 + lb) * HST) * 4u
                              + dst_lane_off;
                #pragma unroll
                for (int i = 0; i < 8; i++) {
                    asm volatile("cp.async.cg.shared.global [%0], [%1], 16;"
                                 :: "r"(dstN + (unsigned)(8 * i * HST) * 4u),
                                    "l"(srcN + (size_t)(8 * i) * H_SZ) : "memory");
                }
                asm volatile("cp.async.commit_group;" ::: "memory");
                asm volatile("cp.async.wait_group 1;" ::: "memory");
            } else {
                asm volatile("cp.async.wait_group 0;" ::: "memory");
            }
            __syncwarp();   // chunk c visible to every lane

            const float* hbase = &HwW[buf * 64 * HST];
            const float* wbase = &Ws[kofs + c * CHK];
            #pragma unroll
            for (int u = 0; u < CHK / 4; u++) {
                ulonglong2 hA = *(const ulonglong2*)&hbase[lane * HST + u * 4];
                ulonglong2 hB = *(const ulonglong2*)&hbase[(lane + 32) * HST + u * 4];
                #pragma unroll
                for (int row = 0; row < NROW; row++) {
                    ulonglong2 wv = *(const ulonglong2*)&wbase[row * H_SZ + u * 4];
                    ffma2(acc[row][0], hA.x, wv.x);
                    ffma2(acc[row][0], hA.y, wv.y);
                    ffma2(acc[row][1], hB.x, wv.x);
                    ffma2(acc[row][1], hB.y, wv.y);
                }
            }
        }

        // partials -> Red[w][row][b]
        #pragma unroll
        for (int row = 0; row < NROW; row++) {
            float* R = Red + (size_t)(w * NROW + row) * REDS;
            R[lane]      = sum2(acc[row][0]);
            R[lane + 32] = sum2(acc[row][1]);
        }
        __syncthreads();

        // fused gate epilogue: 2 outputs per thread
        #pragma unroll
        for (int e = 0; e < 2; e++) {
            int o   = tid + e * 256;
            int eb  = o >> 3;
            int ejj = o & 7;
            float sr = 0.f, sz = 0.f, sn = 0.f;
            #pragma unroll
            for (int s = 0; s < NWARP; s++) {
                const float* R = Red + (size_t)s * NROW * REDS;
                sr += R[(0 * 8 + ejj) * REDS + eb];
                sz += R[(1 * 8 + ejj) * REDS + eb];
                sn += R[(2 * 8 + ejj) * REDS + eb];
            }
            float r = 1.f / (1.f + expf(-(xr[e] + sr + bh[e][0])));
            float z = 1.f / (1.f + expf(-(xz[e] + sz + bh[e][1])));
            float n = tanhf(xn[e] + r * (sn + bh[e][2]));
            float hnew = (1.f - z) * n + z * hpv[e];
            __stcg(&ho[(size_t)eb * H_SZ + j0 + ejj], hnew);
            if (t == T_LEN - 1)
                __stcg(&hn_out[(size_t)eb * H_SZ + j0 + ejj], hnew);
            hpv[e] = hnew;
        }

        // ---- grid-wide sync ----
        __threadfence();
        __syncthreads();
        if (tid == 0) {
            asm volatile("red.release.gpu.global.add.u32 [%0], %1;"
                         :: "l"(&g_sync), "r"(1u) : "memory");
            unsigned v;
            do {
                asm volatile("ld.acquire.gpu.global.u32 %0, [%1];"
                             : "=r"(v) : "l"(&g_sync) : "memory");
            } while (v < target);
        }
        __syncthreads();
        target += NBLK;
    }
}

extern "C" void kernel_launch(void* const* d_in, const int* in_sizes, int n_in,
                              void* d_out, int out_size)
{
    const float* x    = (const float*)d_in[0];   // (T, B, I)
    const float* w_ih = (const float*)d_in[1];   // (3H, I)
    const float* w_hh = (const float*)d_in[2];   // (3H, H)
    const float* b_ih = (const float*)d_in[3];   // (3H,)
    const float* b_hh = (const float*)d_in[4];   // (3H,)
    float* out = (float*)d_out;

    // reset the grid-sync counter (graph-capturable H2D memcpy)
    static unsigned h_zero = 0;
    void* sync_addr = nullptr;
    cudaGetSymbolAddress(&sync_addr, g_sync);
    cudaMemcpyAsync(sync_addr, &h_zero, sizeof(unsigned),
                    cudaMemcpyHostToDevice, 0);

    // Phase 1: input projection GEMM
    dim3 gridA(G3H / 128, M_TOT / 128);
    gemm_xgates<<<gridA, 256>>>(x, w_ih, b_ih);

    // Phase 2: persistent recurrent scan (all 512 steps in one kernel)
    const int smem_bytes = (NROW * H_SZ + NWARP * 2 * 64 * HST
                            + NWARP * NROW * REDS) * (int)sizeof(float);
    cudaFuncSetAttribute(gru_persistent,
                         cudaFuncAttributeMaxDynamicSharedMemorySize, smem_bytes);
    gru_persistent<<<NBLK, 256, smem_bytes>>>(out, w_hh, b_hh);
}

// round 13
// speedup vs baseline: 6.3724x; 1.3091x over previous
#include <cuda_runtime.h>
#include <cuda_bf16.h>
#include <math.h>
#include <stdint.h>

// Problem constants
#define T_LEN 512
#define B_SZ  64
#define I_SZ  512
#define H_SZ  1024
#define G3H   3072
#define M_TOT 32768          // T*B

#define NBLK  128            // persistent blocks (1 per SM)
#define JT    8              // hidden units per block
#define NROW  24             // gate rows per block

// scan smem (bytes): A buffers then Red
#define AROWB   48                    // bytes per staged row (16 bf16 + pad)
#define ABUF    (64 * AROWB)          // 3072 B, one (buf,hilo) plane
#define WARPA   (4 * ABUF)            // 2 buf x 2 hilo = 12288 B per warp
#define OFF_RED (8 * WARPA)           // 98304
#define REDW    26                    // Red row stride (floats)
#define SMEM_SCAN (OFF_RED + 8 * 64 * REDW * 4)   // 151552

typedef unsigned long long ull;

__device__ __align__(16) float g_gates[(size_t)M_TOT * G3H];
__device__ __align__(16) float g_h0[B_SZ * H_SZ];           // zeros, never written
__device__ __align__(16) unsigned short g_hhi[B_SZ * H_SZ]; // h bf16 hi
__device__ __align__(16) unsigned short g_hlo[B_SZ * H_SZ]; // h bf16 lo
__device__ unsigned g_sync;

// ---------------------------------------------------------------------------
// helpers
// ---------------------------------------------------------------------------
__device__ __forceinline__ ull dup2(float w) {
    ull r; asm("mov.b64 %0, {%1, %1};" : "=l"(r) : "f"(w)); return r;
}
__device__ __forceinline__ void ffma2(ull& d, ull a, ull b) {
    asm("fma.rn.f32x2 %0, %1, %2, %0;" : "+l"(d) : "l"(a), "l"(b));
}
__device__ __forceinline__ void unpack2(ull v, float& lo, float& hi) {
    asm("mov.b64 {%0, %1}, %2;" : "=f"(lo), "=f"(hi) : "l"(v));
}
__device__ __forceinline__ void mma16816(float* d, const unsigned* a,
                                         const unsigned* b) {
    asm volatile(
        "mma.sync.aligned.m16n8k16.row.col.f32.bf16.bf16.f32 "
        "{%0,%1,%2,%3}, {%4,%5,%6,%7}, {%8,%9}, {%0,%1,%2,%3};"
        : "+f"(d[0]), "+f"(d[1]), "+f"(d[2]), "+f"(d[3])
        : "r"(a[0]), "r"(a[1]), "r"(a[2]), "r"(a[3]), "r"(b[0]), "r"(b[1]));
}
__device__ __forceinline__ void ldmat4(unsigned* r, uint32_t addr) {
    asm volatile("ldmatrix.sync.aligned.m8n8.x4.shared.b16 {%0,%1,%2,%3}, [%4];"
                 : "=r"(r[0]), "=r"(r[1]), "=r"(r[2]), "=r"(r[3]) : "r"(addr));
}
__device__ __forceinline__ unsigned pack_bf2(float a, float b) {
    __nv_bfloat16 x = __float2bfloat16_rn(a);
    __nv_bfloat16 y = __float2bfloat16_rn(b);
    return (unsigned)__bfloat16_as_ushort(x)
         | ((unsigned)__bfloat16_as_ushort(y) << 16);
}

// ---------------------------------------------------------------------------
// Kernel A: x_gates = x @ w_ih^T + b_ih (unchanged best SIMT f32x2)
// ---------------------------------------------------------------------------
__global__ __launch_bounds__(256)
void gemm_xgates(const float* __restrict__ A,
                 const float* __restrict__ W,
                 const float* __restrict__ bias)
{
    __shared__ __align__(16) float As[2][8][132];
    __shared__ __align__(16) float Bs[2][8][132];

    const int m0 = blockIdx.y * 128;
    const int n0 = blockIdx.x * 128;
    const int tid = threadIdx.x;
    const int tm = tid >> 4;
    const int tn = tid & 15;
    const int lr = tid >> 1;
    const int lk4 = (tid & 1) * 4;

    ull acc[8][4];
    #pragma unroll
    for (int i = 0; i < 8; i++)
        #pragma unroll
        for (int p = 0; p < 4; p++) acc[i][p] = 0ull;

    float4 av = *(const float4*)&A[(size_t)(m0 + lr) * I_SZ + lk4];
    float4 wv = *(const float4*)&W[(size_t)(n0 + lr) * I_SZ + lk4];
    {
        As[0][lk4 + 0][lr] = av.x; As[0][lk4 + 1][lr] = av.y;
        As[0][lk4 + 2][lr] = av.z; As[0][lk4 + 3][lr] = av.w;
        Bs[0][lk4 + 0][lr] = wv.x; Bs[0][lk4 + 1][lr] = wv.y;
        Bs[0][lk4 + 2][lr] = wv.z; Bs[0][lk4 + 3][lr] = wv.w;
    }
    __syncthreads();

    #pragma unroll 1
    for (int kt = 0; kt < 64; kt++) {
        const int buf = kt & 1;
        if (kt < 63) {
            int k0 = (kt + 1) * 8 + lk4;
            av = *(const float4*)&A[(size_t)(m0 + lr) * I_SZ + k0];
            wv = *(const float4*)&W[(size_t)(n0 + lr) * I_SZ + k0];
        }
        #pragma unroll
        for (int kk = 0; kk < 8; kk++) {
            float4 a0 = *(const float4*)&As[buf][kk][tm * 8];
            float4 a1 = *(const float4*)&As[buf][kk][tm * 8 + 4];
            ull am[8];
            am[0] = dup2(a0.x); am[1] = dup2(a0.y);
            am[2] = dup2(a0.z); am[3] = dup2(a0.w);
            am[4] = dup2(a1.x); am[5] = dup2(a1.y);
            am[6] = dup2(a1.z); am[7] = dup2(a1.w);
            ulonglong2 b0 = *(const ulonglong2*)&Bs[buf][kk][tn * 8];
            ulonglong2 b1 = *(const ulonglong2*)&Bs[buf][kk][tn * 8 + 4];
            #pragma unroll
            for (int i = 0; i < 8; i++) {
                ffma2(acc[i][0], am[i], b0.x);
                ffma2(acc[i][1], am[i], b0.y);
                ffma2(acc[i][2], am[i], b1.x);
                ffma2(acc[i][3], am[i], b1.y);
            }
        }
        if (kt < 63) {
            const int nb = buf ^ 1;
            As[nb][lk4 + 0][lr] = av.x; As[nb][lk4 + 1][lr] = av.y;
            As[nb][lk4 + 2][lr] = av.z; As[nb][lk4 + 3][lr] = av.w;
            Bs[nb][lk4 + 0][lr] = wv.x; Bs[nb][lk4 + 1][lr] = wv.y;
            Bs[nb][lk4 + 2][lr] = wv.z; Bs[nb][lk4 + 3][lr] = wv.w;
        }
        __syncthreads();
    }

    const int nn = n0 + tn * 8;
    float4 bv0 = *(const float4*)&bias[nn];
    float4 bv1 = *(const float4*)&bias[nn + 4];
    #pragma unroll
    for (int i = 0; i < 8; i++) {
        float c0, c1, c2, c3, c4, c5, c6, c7;
        unpack2(acc[i][0], c0, c1);
        unpack2(acc[i][1], c2, c3);
        unpack2(acc[i][2], c4, c5);
        unpack2(acc[i][3], c6, c7);
        float4 o0 = make_float4(c0 + bv0.x, c1 + bv0.y, c2 + bv0.z, c3 + bv0.w);
        float4 o1 = make_float4(c4 + bv1.x, c5 + bv1.y, c6 + bv1.z, c7 + bv1.w);
        int row = m0 + tm * 8 + i;
        *(float4*)&g_gates[(size_t)row * G3H + nn]     = o0;
        *(float4*)&g_gates[(size_t)row * G3H + nn + 4] = o1;
    }
}

// ---------------------------------------------------------------------------
// Persistent GRU scan via mma.sync bf16 hi/lo.
// 128 blocks, 256 threads (8 warps).  Warp w: real-K slice [128w, 128w+128),
// all 24 gate rows.  W as register-resident B-fragments (hi+lo).
// Per k-tile: cp.async-stage h hi/lo (64x16 bf16), ldmatrix A frags,
// 36 HMMA (Ah*Wh + Ah*Wl + Al*Wh).  Cross-warp reduce in smem, fused gates.
// ---------------------------------------------------------------------------
__global__ void __launch_bounds__(256, 1)
gru_scan_mma(float* __restrict__ out,
             const float* __restrict__ w_hh,
             const float* __restrict__ b_hh)
{
    extern __shared__ __align__(16) char smem[];
    uint32_t sm32 = (uint32_t)__cvta_generic_to_shared((void*)smem);
    float* Red = (float*)(smem + OFF_RED);

    const int tid  = threadIdx.x;
    const int w    = tid >> 5;
    const int lane = tid & 31;
    const int j0   = blockIdx.x * JT;
    const int kofs = w * 128;             // real-k base for this warp

    // ---- build W B-fragments in registers (once) ----
    // b-frag for (nt, kt): reg0 = W[n][k0..k0+1], reg1 = W[n][k0+8..k0+9]
    // with n = nt*8 + (lane>>2), k0 = kofs + kt*16 + (lane&3)*2
    unsigned Whi[3][8][2], Wlo[3][8][2];
    {
        const int nl = lane >> 2;
        const int kl = (lane & 3) * 2;
        #pragma unroll
        for (int nt = 0; nt < 3; nt++) {
            int n = nt * 8 + nl;
            int g = n >> 3, jj = n & 7;
            const float* wr = &w_hh[(size_t)(g * H_SZ + j0 + jj) * H_SZ];
            #pragma unroll
            for (int kt = 0; kt < 8; kt++) {
                int k0 = kofs + kt * 16 + kl;
                float v0 = wr[k0],     v1 = wr[k0 + 1];
                float v2 = wr[k0 + 8], v3 = wr[k0 + 9];
                float h0 = __bfloat162float(__float2bfloat16_rn(v0));
                float h1 = __bfloat162float(__float2bfloat16_rn(v1));
                float h2 = __bfloat162float(__float2bfloat16_rn(v2));
                float h3 = __bfloat162float(__float2bfloat16_rn(v3));
                Whi[nt][kt][0] = pack_bf2(v0, v1);
                Whi[nt][kt][1] = pack_bf2(v2, v3);
                Wlo[nt][kt][0] = pack_bf2(v0 - h0, v1 - h1);
                Wlo[nt][kt][1] = pack_bf2(v2 - h2, v3 - h3);
            }
        }
    }

    // ---- epilogue mapping: outputs o = tid, tid+256 ----
    float bh[2][3];
    #pragma unroll
    for (int e = 0; e < 2; e++) {
        int o = tid + e * 256;
        int ej = j0 + (o & 7);
        bh[e][0] = b_hh[ej];
        bh[e][1] = b_hh[H_SZ + ej];
        bh[e][2] = b_hh[2 * H_SZ + ej];
    }

    // A staging constants (warp-private buffers)
    const uint32_t abase = sm32 + (uint32_t)(w * WARPA);
    // ldmatrix row address: batch = mt*16 + (lane&15), half = lane>>4
    const uint32_t lm_off = (uint32_t)((lane & 15) * AROWB + (lane >> 4) * 16);

    __syncthreads();

    unsigned target = NBLK;
    float* hn_out = out + (size_t)T_LEN * B_SZ * H_SZ;
    float hpv[2] = {0.f, 0.f};

    #pragma unroll 1
    for (int t = 0; t < T_LEN; t++) {
        const unsigned short* hhi = (t == 0) ? (const unsigned short*)g_h0 : g_hhi;
        const unsigned short* hlo = (t == 0) ? (const unsigned short*)g_h0 : g_hlo;
        float* ho = out + (size_t)t * B_SZ * H_SZ;

        // x-gate prefetch (overlaps mainloop)
        float xr[2], xz[2], xn[2];
        #pragma unroll
        for (int e = 0; e < 2; e++) {
            int o = tid + e * 256;
            const float* xg = g_gates + (size_t)t * B_SZ * G3H
                            + (size_t)(o >> 3) * G3H + j0 + (o & 7);
            xr[e] = __ldcg(&xg[0]);
            xz[e] = __ldcg(&xg[H_SZ]);
            xn[e] = __ldcg(&xg[2 * H_SZ]);
        }

        float acc[4][3][4];
        #pragma unroll
        for (int mt = 0; mt < 4; mt++)
            #pragma unroll
            for (int nt = 0; nt < 3; nt++)
                #pragma unroll
                for (int i = 0; i < 4; i++) acc[mt][nt][i] = 0.f;

        // ---- stage k-tile 0 into buf 0 ----
        {
            const int ktk = kofs;
            #pragma unroll
            for (int i = 0; i < 4; i++) {
                int chunk = lane + 32 * i;      // 0..127
                int row   = chunk >> 1;
                int half  = chunk & 1;
                uint32_t dst = abase + (uint32_t)(row * AROWB + half * 16);
                asm volatile("cp.async.cg.shared.global [%0], [%1], 16;"
                             :: "r"(dst),
                                "l"(hhi + (size_t)row * H_SZ + ktk + half * 8)
                             : "memory");
                asm volatile("cp.async.cg.shared.global [%0], [%1], 16;"
                             :: "r"(dst + ABUF),
                                "l"(hlo + (size_t)row * H_SZ + ktk + half * 8)
                             : "memory");
            }
            asm volatile("cp.async.commit_group;" ::: "memory");
        }

        #pragma unroll 1
        for (int kt = 0; kt < 8; kt++) {
            const int buf = kt & 1;
            __syncwarp();
            if (kt < 7) {
                const int ktk = kofs + (kt + 1) * 16;
                uint32_t bb = abase + (uint32_t)((buf ^ 1) * 2 * ABUF);
                #pragma unroll
                for (int i = 0; i < 4; i++) {
                    int chunk = lane + 32 * i;
                    int row   = chunk >> 1;
                    int half  = chunk & 1;
                    uint32_t dst = bb + (uint32_t)(row * AROWB + half * 16);
                    asm volatile("cp.async.cg.shared.global [%0], [%1], 16;"
                                 :: "r"(dst),
                                    "l"(hhi + (size_t)row * H_SZ + ktk + half * 8)
                                 : "memory");
                    asm volatile("cp.async.cg.shared.global [%0], [%1], 16;"
                                 :: "r"(dst + ABUF),
                                    "l"(hlo + (size_t)row * H_SZ + ktk + half * 8)
                                 : "memory");
                }
                asm volatile("cp.async.commit_group;" ::: "memory");
                asm volatile("cp.async.wait_group 1;" ::: "memory");
            } else {
                asm volatile("cp.async.wait_group 0;" ::: "memory");
            }
            __syncwarp();

            const uint32_t hibuf = abase + (uint32_t)(buf * 2 * ABUF) + lm_off;
            const uint32_t lobuf = hibuf + ABUF;
            #pragma unroll
            for (int mt = 0; mt < 4; mt++) {
                unsigned Ah[4], Al[4];
                ldmat4(Ah, hibuf + (uint32_t)(mt * 16 * AROWB));
                ldmat4(Al, lobuf + (uint32_t)(mt * 16 * AROWB));
                #pragma unroll
                for (int nt = 0; nt < 3; nt++) {
                    mma16816(acc[mt][nt], Ah, Whi[nt][kt]);
                    mma16816(acc[mt][nt], Ah, Wlo[nt][kt]);
                    mma16816(acc[mt][nt], Al, Whi[nt][kt]);
                }
            }
        }

        // ---- D frags -> Red[w][batch][row24] ----
        // c0,c1: (batch = mt*16 + lane>>2, rows nt*8 + (lane&3)*2, +1)
        // c2,c3: batch + 8
        {
            float* Rw = Red + (size_t)w * 64 * REDW;
            const int br = lane >> 2;
            const int cl = (lane & 3) * 2;
            #pragma unroll
            for (int mt = 0; mt < 4; mt++) {
                #pragma unroll
                for (int nt = 0; nt < 3; nt++) {
                    *(float2*)&Rw[(mt * 16 + br) * REDW + nt * 8 + cl] =
                        make_float2(acc[mt][nt][0], acc[mt][nt][1]);
                    *(float2*)&Rw[(mt * 16 + br + 8) * REDW + nt * 8 + cl] =
                        make_float2(acc[mt][nt][2], acc[mt][nt][3]);
                }
            }
        }
        __syncthreads();

        // ---- fused gate epilogue: 2 outputs per thread ----
        #pragma unroll
        for (int e = 0; e < 2; e++) {
            int o   = tid + e * 256;
            int eb  = o >> 3;
            int ejj = o & 7;
            float sr = 0.f, sz = 0.f, sn = 0.f;
            #pragma unroll
            for (int s = 0; s < 8; s++) {
                const float* R = Red + ((size_t)s * 64 + eb) * REDW;
                sr += R[ejj];
                sz += R[8 + ejj];
                sn += R[16 + ejj];
            }
            float r = 1.f / (1.f + expf(-(xr[e] + sr + bh[e][0])));
            float z = 1.f / (1.f + expf(-(xz[e] + sz + bh[e][1])));
            float n = tanhf(xn[e] + r * (sn + bh[e][2]));
            float hnew = (1.f - z) * n + z * hpv[e];
            hpv[e] = hnew;
            size_t oidx = (size_t)eb * H_SZ + j0 + ejj;
            __stcg(&ho[oidx], hnew);
            if (t == T_LEN - 1) __stcg(&hn_out[oidx], hnew);
            // bf16 hi/lo for next step
            __nv_bfloat16 bhh = __float2bfloat16_rn(hnew);
            float fh = __bfloat162float(bhh);
            __nv_bfloat16 bll = __float2bfloat16_rn(hnew - fh);
            g_hhi[oidx] = __bfloat16_as_ushort(bhh);
            g_hlo[oidx] = __bfloat16_as_ushort(bll);
        }

        // ---- grid-wide sync ----
        __threadfence();
        __syncthreads();
        if (tid == 0) {
            asm volatile("red.release.gpu.global.add.u32 [%0], %1;"
                         :: "l"(&g_sync), "r"(1u) : "memory");
            unsigned vv;
            do {
                asm volatile("ld.acquire.gpu.global.u32 %0, [%1];"
                             : "=r"(vv) : "l"(&g_sync) : "memory");
            } while (vv < target);
        }
        __syncthreads();
        target += NBLK;
    }
}

extern "C" void kernel_launch(void* const* d_in, const int* in_sizes, int n_in,
                              void* d_out, int out_size)
{
    const float* x    = (const float*)d_in[0];   // (T, B, I)
    const float* w_ih = (const float*)d_in[1];   // (3H, I)
    const float* w_hh = (const float*)d_in[2];   // (3H, H)
    const float* b_ih = (const float*)d_in[3];   // (3H,)
    const float* b_hh = (const float*)d_in[4];   // (3H,)
    float* out = (float*)d_out;

    // reset the grid-sync counter (graph-capturable H2D memcpy)
    static unsigned h_zero = 0;
    void* sync_addr = nullptr;
    cudaGetSymbolAddress(&sync_addr, g_sync);
    cudaMemcpyAsync(sync_addr, &h_zero, sizeof(unsigned),
                    cudaMemcpyHostToDevice, 0);

    // Phase 1: input projection GEMM
    dim3 gridA(G3H / 128, M_TOT / 128);
    gemm_xgates<<<gridA, 256>>>(x, w_ih, b_ih);

    // Phase 2: persistent tensor-core (mma.sync) recurrent scan
    cudaFuncSetAttribute(gru_scan_mma,
                         cudaFuncAttributeMaxDynamicSharedMemorySize, SMEM_SCAN);
    gru_scan_mma<<<NBLK, 256, SMEM_SCAN>>>(out, w_hh, b_hh);
}

// round 14
// speedup vs baseline: 7.3076x; 1.1467x over previous
#include <cuda_runtime.h>
#include <cuda_bf16.h>
#include <math.h>
#include <stdint.h>

// Problem constants
#define T_LEN 512
#define B_SZ  64
#define I_SZ  512
#define H_SZ  1024
#define G3H   3072
#define M_TOT 32768          // T*B

#define NBLK  128            // persistent blocks (1 per SM)
#define JT    8              // hidden units per block
#define NROW  24             // gate rows per block

// ---- scan smem (bytes): 3-deep A buffers then Red ----
#define AROWB   48                    // bytes per staged row (16 bf16 + pad)
#define ABUF    (64 * AROWB)          // 3072 B, one (buf,hilo) plane
#define WARPA   (3 * 2 * ABUF)        // 3 buf x 2 hilo = 18432 B per warp
#define OFF_RED (8 * WARPA)           // 147456
#define REDW    26                    // Red row stride (floats)
#define SMEM_SCAN (OFF_RED + 8 * 64 * REDW * 4)   // 200704

// ---- gemm smem (bytes) ----
#define GA_PLANE (128 * 48)           // 6144
#define GB_PLANE (64 * 48)            // 3072
#define GBUF     (2 * GA_PLANE + 2 * GB_PLANE)   // 18432
#define SMEM_GEMM (2 * GBUF)          // 36864

typedef unsigned long long ull;
typedef unsigned short u16;

__device__ __align__(16) float g_gates[(size_t)M_TOT * G3H];
__device__ __align__(16) float g_h0[B_SZ * H_SZ];           // zeros, never written
__device__ __align__(16) u16 g_hhi[B_SZ * H_SZ];            // h bf16 hi
__device__ __align__(16) u16 g_hlo[B_SZ * H_SZ];            // h bf16 lo
__device__ __align__(16) u16 g_xhi[(size_t)M_TOT * I_SZ];   // x bf16 hi
__device__ __align__(16) u16 g_xlo[(size_t)M_TOT * I_SZ];   // x bf16 lo
__device__ __align__(16) u16 g_whi[(size_t)G3H * I_SZ];     // w_ih bf16 hi
__device__ __align__(16) u16 g_wlo[(size_t)G3H * I_SZ];     // w_ih bf16 lo
__device__ unsigned g_sync;

// ---------------------------------------------------------------------------
// helpers
// ---------------------------------------------------------------------------
__device__ __forceinline__ void mma16816(float* d, const unsigned* a,
                                         const unsigned* b) {
    asm volatile(
        "mma.sync.aligned.m16n8k16.row.col.f32.bf16.bf16.f32 "
        "{%0,%1,%2,%3}, {%4,%5,%6,%7}, {%8,%9}, {%0,%1,%2,%3};"
        : "+f"(d[0]), "+f"(d[1]), "+f"(d[2]), "+f"(d[3])
        : "r"(a[0]), "r"(a[1]), "r"(a[2]), "r"(a[3]), "r"(b[0]), "r"(b[1]));
}
__device__ __forceinline__ void ldmat4(unsigned* r, uint32_t addr) {
    asm volatile("ldmatrix.sync.aligned.m8n8.x4.shared.b16 {%0,%1,%2,%3}, [%4];"
                 : "=r"(r[0]), "=r"(r[1]), "=r"(r[2]), "=r"(r[3]) : "r"(addr));
}
__device__ __forceinline__ unsigned pack_bf2(float a, float b) {
    __nv_bfloat16 x = __float2bfloat16_rn(a);
    __nv_bfloat16 y = __float2bfloat16_rn(b);
    return (unsigned)__bfloat16_as_ushort(x)
         | ((unsigned)__bfloat16_as_ushort(y) << 16);
}
#define CP16(dst, src) \
    asm volatile("cp.async.cg.shared.global [%0], [%1], 16;" \
                 :: "r"(dst), "l"(src) : "memory")
#define CP_COMMIT() asm volatile("cp.async.commit_group;" ::: "memory")
#define CP_WAIT(n)  asm volatile("cp.async.wait_group %0;" :: "n"(n) : "memory")

// ---------------------------------------------------------------------------
// Conversion: f32 -> bf16 hi/lo
// ---------------------------------------------------------------------------
__global__ void cvt_hilo(const float* __restrict__ src,
                         u16* __restrict__ hi, u16* __restrict__ lo, int n4)
{
    int i = blockIdx.x * 256 + threadIdx.x;
    if (i >= n4) return;
    float4 v = ((const float4*)src)[i];
    unsigned h0 = pack_bf2(v.x, v.y);
    unsigned h1 = pack_bf2(v.z, v.w);
    float rx = v.x - __bfloat162float(__ushort_as_bfloat16((u16)h0));
    float ry = v.y - __bfloat162float(__ushort_as_bfloat16((u16)(h0 >> 16)));
    float rz = v.z - __bfloat162float(__ushort_as_bfloat16((u16)h1));
    float rw = v.w - __bfloat162float(__ushort_as_bfloat16((u16)(h1 >> 16)));
    ((uint2*)hi)[i] = make_uint2(h0, h1);
    ((uint2*)lo)[i] = make_uint2(pack_bf2(rx, ry), pack_bf2(rz, rw));
}

// ---------------------------------------------------------------------------
// Kernel A: x_gates = x @ w_ih^T + b_ih via mma.sync bf16 hi/lo (3-pass).
// Block tile M=128, N=64; 256 threads / 8 warps (wm = w&3: 32 rows,
// wn = w>>2: 32 cols).  Double-buffered cp.async staging.
// ---------------------------------------------------------------------------
__global__ __launch_bounds__(256)
void gemm_xgates_mma(const float* __restrict__ bias)
{
    extern __shared__ __align__(16) char smem[];
    uint32_t sm32 = (uint32_t)__cvta_generic_to_shared((void*)smem);

    const int tid  = threadIdx.x;
    const int w    = tid >> 5;
    const int lane = tid & 31;
    const int wm   = w & 3;
    const int wn   = w >> 2;
    const int m0   = blockIdx.y * 128;
    const int n0   = blockIdx.x * 64;

    // staging indices
    const int arow = tid >> 1, akh = tid & 1;                 // A: 1 chunk/plane
    const int bhl = tid >> 7, brem = tid & 127;               // B: 1 chunk total
    const int brow = brem >> 1, bkh = brem & 1;

    float acc[2][4][4];
    #pragma unroll
    for (int mt = 0; mt < 2; mt++)
        #pragma unroll
        for (int nt = 0; nt < 4; nt++)
            #pragma unroll
            for (int i = 0; i < 4; i++) acc[mt][nt][i] = 0.f;

    // stage k-tile kt into buffer buf
    auto stage = [&](int kt, int buf) {
        const int k0 = kt * 16;
        uint32_t bb = sm32 + (uint32_t)(buf * GBUF);
        // A hi/lo
        uint32_t adst = bb + (uint32_t)(arow * 48 + akh * 16);
        const size_t asrc = (size_t)(m0 + arow) * I_SZ + k0 + akh * 8;
        CP16(adst,            g_xhi + asrc);
        CP16(adst + GA_PLANE, g_xlo + asrc);
        // B (hi or lo depending on thread half)
        uint32_t bdst = bb + (uint32_t)(2 * GA_PLANE + bhl * GB_PLANE
                                        + brow * 48 + bkh * 16);
        const u16* bsrc = (bhl ? g_wlo : g_whi)
                        + (size_t)(n0 + brow) * I_SZ + k0 + bkh * 8;
        CP16(bdst, bsrc);
    };

    stage(0, 0);
    CP_COMMIT();

    const uint32_t lmA = (uint32_t)((wm * 32 + (lane & 15)) * 48
                                    + (lane >> 4) * 16);
    const int bnr = wn * 32 + (lane >> 2);
    const int bkl = (lane & 3) * 4;

    #pragma unroll 1
    for (int kt = 0; kt < 32; kt++) {
        const int buf = kt & 1;
        if (kt < 31) { stage(kt + 1, buf ^ 1); }
        CP_COMMIT();
        CP_WAIT(1);
        __syncthreads();

        uint32_t bb = sm32 + (uint32_t)(buf * GBUF);
        const char* bgen = smem + (size_t)buf * GBUF;

        unsigned Bh[4][2], Bl[4][2];
        #pragma unroll
        for (int nt = 0; nt < 4; nt++) {
            const char* p = bgen + 2 * GA_PLANE + (bnr + nt * 8) * 48 + bkl;
            Bh[nt][0] = *(const unsigned*)p;
            Bh[nt][1] = *(const unsigned*)(p + 16);
            Bl[nt][0] = *(const unsigned*)(p + GB_PLANE);
            Bl[nt][1] = *(const unsigned*)(p + GB_PLANE + 16);
        }
        #pragma unroll
        for (int mt = 0; mt < 2; mt++) {
            unsigned Ah[4], Al[4];
            ldmat4(Ah, bb + lmA + (uint32_t)(mt * 16 * 48));
            ldmat4(Al, bb + GA_PLANE + lmA + (uint32_t)(mt * 16 * 48));
            #pragma unroll
            for (int nt = 0; nt < 4; nt++) {
                mma16816(acc[mt][nt], Ah, Bh[nt]);
                mma16816(acc[mt][nt], Ah, Bl[nt]);
                mma16816(acc[mt][nt], Al, Bh[nt]);
            }
        }
        __syncthreads();
    }

    // epilogue: D frags + bias -> g_gates
    #pragma unroll
    for (int nt = 0; nt < 4; nt++) {
        int col = n0 + wn * 32 + nt * 8 + (lane & 3) * 2;
        float2 bv = *(const float2*)&bias[col];
        #pragma unroll
        for (int mt = 0; mt < 2; mt++) {
            int row = m0 + wm * 32 + mt * 16 + (lane >> 2);
            *(float2*)&g_gates[(size_t)row * G3H + col] =
                make_float2(acc[mt][nt][0] + bv.x, acc[mt][nt][1] + bv.y);
            *(float2*)&g_gates[(size_t)(row + 8) * G3H + col] =
                make_float2(acc[mt][nt][2] + bv.x, acc[mt][nt][3] + bv.y);
        }
    }
}

// ---------------------------------------------------------------------------
// Persistent GRU scan via mma.sync bf16 hi/lo, depth-3 cp.async pipeline.
// 128 blocks, 256 threads (8 warps).  Warp w: real-K slice [128w, 128w+128),
// all 24 gate rows; W as register-resident B-fragments (hi+lo).
// ---------------------------------------------------------------------------
__global__ void __launch_bounds__(256, 1)
gru_scan_mma(float* __restrict__ out,
             const float* __restrict__ w_hh,
             const float* __restrict__ b_hh)
{
    extern __shared__ __align__(16) char smem[];
    uint32_t sm32 = (uint32_t)__cvta_generic_to_shared((void*)smem);
    float* Red = (float*)(smem + OFF_RED);

    const int tid  = threadIdx.x;
    const int w    = tid >> 5;
    const int lane = tid & 31;
    const int j0   = blockIdx.x * JT;
    const int kofs = w * 128;

    // ---- W B-fragments in registers (once) ----
    unsigned Whi[3][8][2], Wlo[3][8][2];
    {
        const int nl = lane >> 2;
        const int kl = (lane & 3) * 2;
        #pragma unroll
        for (int nt = 0; nt < 3; nt++) {
            int n = nt * 8 + nl;
            int g = n >> 3, jj = n & 7;
            const float* wr = &w_hh[(size_t)(g * H_SZ + j0 + jj) * H_SZ];
            #pragma unroll
            for (int kt = 0; kt < 8; kt++) {
                int k0 = kofs + kt * 16 + kl;
                float v0 = wr[k0],     v1 = wr[k0 + 1];
                float v2 = wr[k0 + 8], v3 = wr[k0 + 9];
                float h0 = __bfloat162float(__float2bfloat16_rn(v0));
                float h1 = __bfloat162float(__float2bfloat16_rn(v1));
                float h2 = __bfloat162float(__float2bfloat16_rn(v2));
                float h3 = __bfloat162float(__float2bfloat16_rn(v3));
                Whi[nt][kt][0] = pack_bf2(v0, v1);
                Whi[nt][kt][1] = pack_bf2(v2, v3);
                Wlo[nt][kt][0] = pack_bf2(v0 - h0, v1 - h1);
                Wlo[nt][kt][1] = pack_bf2(v2 - h2, v3 - h3);
            }
        }
    }

    float bh[2][3];
    #pragma unroll
    for (int e = 0; e < 2; e++) {
        int o = tid + e * 256;
        int ej = j0 + (o & 7);
        bh[e][0] = b_hh[ej];
        bh[e][1] = b_hh[H_SZ + ej];
        bh[e][2] = b_hh[2 * H_SZ + ej];
    }

    const uint32_t abase = sm32 + (uint32_t)(w * WARPA);
    const uint32_t lm_off = (uint32_t)((lane & 15) * AROWB + (lane >> 4) * 16);

    __syncthreads();

    unsigned target = NBLK;
    float* hn_out = out + (size_t)T_LEN * B_SZ * H_SZ;
    float hpv[2] = {0.f, 0.f};

    #pragma unroll 1
    for (int t = 0; t < T_LEN; t++) {
        const u16* hhi = (t == 0) ? (const u16*)g_h0 : g_hhi;
        const u16* hlo = (t == 0) ? (const u16*)g_h0 : g_hlo;
        float* ho = out + (size_t)t * B_SZ * H_SZ;

        float xr[2], xz[2], xn[2];
        #pragma unroll
        for (int e = 0; e < 2; e++) {
            int o = tid + e * 256;
            const float* xg = g_gates + (size_t)t * B_SZ * G3H
                            + (size_t)(o >> 3) * G3H + j0 + (o & 7);
            xr[e] = __ldcg(&xg[0]);
            xz[e] = __ldcg(&xg[H_SZ]);
            xn[e] = __ldcg(&xg[2 * H_SZ]);
        }

        float acc[4][3][4];
        #pragma unroll
        for (int mt = 0; mt < 4; mt++)
            #pragma unroll
            for (int nt = 0; nt < 3; nt++)
                #pragma unroll
                for (int i = 0; i < 4; i++) acc[mt][nt][i] = 0.f;

        // stage k-tile kt into buffer buf (warp-private)
        auto stageA = [&](int kt, int buf) {
            const int ktk = kofs + kt * 16;
            uint32_t bb = abase + (uint32_t)(buf * 2 * ABUF);
            #pragma unroll
            for (int i = 0; i < 4; i++) {
                int chunk = lane + 32 * i;
                int row   = chunk >> 1;
                int half  = chunk & 1;
                uint32_t dst = bb + (uint32_t)(row * AROWB + half * 16);
                const size_t so = (size_t)row * H_SZ + ktk + half * 8;
                CP16(dst, hhi + so);
                CP16(dst + ABUF, hlo + so);
            }
            CP_COMMIT();
        };

        stageA(0, 0); stageA(1, 1); stageA(2, 2);

        #pragma unroll 1
        for (int kt = 0; kt < 8; kt++) {
            const int buf = kt % 3;
            CP_WAIT(2);          // in-order: tile kt complete
            __syncwarp();

            const uint32_t hibuf = abase + (uint32_t)(buf * 2 * ABUF) + lm_off;
            const uint32_t lobuf = hibuf + ABUF;
            #pragma unroll
            for (int mt = 0; mt < 4; mt++) {
                unsigned Ah[4], Al[4];
                ldmat4(Ah, hibuf + (uint32_t)(mt * 16 * AROWB));
                ldmat4(Al, lobuf + (uint32_t)(mt * 16 * AROWB));
                #pragma unroll
                for (int nt = 0; nt < 3; nt++) {
                    mma16816(acc[mt][nt], Ah, Whi[nt][kt]);
                    mma16816(acc[mt][nt], Ah, Wlo[nt][kt]);
                    mma16816(acc[mt][nt], Al, Whi[nt][kt]);
                }
            }
            __syncwarp();
            if (kt < 5) stageA(kt + 3, buf);
            else        CP_COMMIT();          // empty group keeps wait depth uniform
        }

        // ---- D frags -> Red[w][batch][row24] ----
        {
            float* Rw = Red + (size_t)w * 64 * REDW;
            const int br = lane >> 2;
            const int cl = (lane & 3) * 2;
            #pragma unroll
            for (int mt = 0; mt < 4; mt++) {
                #pragma unroll
                for (int nt = 0; nt < 3; nt++) {
                    *(float2*)&Rw[(mt * 16 + br) * REDW + nt * 8 + cl] =
                        make_float2(acc[mt][nt][0], acc[mt][nt][1]);
                    *(float2*)&Rw[(mt * 16 + br + 8) * REDW + nt * 8 + cl] =
                        make_float2(acc[mt][nt][2], acc[mt][nt][3]);
                }
            }
        }
        __syncthreads();

        // ---- fused gate epilogue: 2 outputs per thread ----
        #pragma unroll
        for (int e = 0; e < 2; e++) {
            int o   = tid + e * 256;
            int eb  = o >> 3;
            int ejj = o & 7;
            float sr = 0.f, sz = 0.f, sn = 0.f;
            #pragma unroll
            for (int s = 0; s < 8; s++) {
                const float* R = Red + ((size_t)s * 64 + eb) * REDW;
                sr += R[ejj];
                sz += R[8 + ejj];
                sn += R[16 + ejj];
            }
            float r = 1.f / (1.f + expf(-(xr[e] + sr + bh[e][0])));
            float z = 1.f / (1.f + expf(-(xz[e] + sz + bh[e][1])));
            float n = tanhf(xn[e] + r * (sn + bh[e][2]));
            float hnew = (1.f - z) * n + z * hpv[e];
            hpv[e] = hnew;
            size_t oidx = (size_t)eb * H_SZ + j0 + ejj;
            __stcg(&ho[oidx], hnew);
            if (t == T_LEN - 1) __stcg(&hn_out[oidx], hnew);
            __nv_bfloat16 bhh = __float2bfloat16_rn(hnew);
            float fh = __bfloat162float(bhh);
            __nv_bfloat16 bll = __float2bfloat16_rn(hnew - fh);
            g_hhi[oidx] = __bfloat16_as_ushort(bhh);
            g_hlo[oidx] = __bfloat16_as_ushort(bll);
        }

        // ---- grid-wide sync ----
        __threadfence();
        __syncthreads();
        if (tid == 0) {
            asm volatile("red.release.gpu.global.add.u32 [%0], %1;"
                         :: "l"(&g_sync), "r"(1u) : "memory");
            unsigned vv;
            do {
                asm volatile("ld.acquire.gpu.global.u32 %0, [%1];"
                             : "=r"(vv) : "l"(&g_sync) : "memory");
            } while (vv < target);
        }
        __syncthreads();
        target += NBLK;
    }
}

extern "C" void kernel_launch(void* const* d_in, const int* in_sizes, int n_in,
                              void* d_out, int out_size)
{
    const float* x    = (const float*)d_in[0];   // (T, B, I)
    const float* w_hh = (const float*)d_in[2];   // (3H, H)
    const float* b_ih = (const float*)d_in[3];   // (3H,)
    const float* b_hh = (const float*)d_in[4];   // (3H,)
    const float* w_ih = (const float*)d_in[1];   // (3H, I)
    float* out = (float*)d_out;

    // reset the grid-sync counter (graph-capturable H2D memcpy)
    static unsigned h_zero = 0;
    void* sync_addr = nullptr;
    cudaGetSymbolAddress(&sync_addr, g_sync);
    cudaMemcpyAsync(sync_addr, &h_zero, sizeof(unsigned),
                    cudaMemcpyHostToDevice, 0);

    // Phase 0: convert x and w_ih to bf16 hi/lo
    u16 *xhi_p, *xlo_p, *whi_p, *wlo_p;
    cudaGetSymbolAddress((void**)&xhi_p, g_xhi);
    cudaGetSymbolAddress((void**)&xlo_p, g_xlo);
    cudaGetSymbolAddress((void**)&whi_p, g_whi);
    cudaGetSymbolAddress((void**)&wlo_p, g_wlo);
    {
        int n4x = M_TOT * I_SZ / 4;
        cvt_hilo<<<(n4x + 255) / 256, 256>>>(x, xhi_p, xlo_p, n4x);
        int n4w = G3H * I_SZ / 4;
        cvt_hilo<<<(n4w + 255) / 256, 256>>>(w_ih, whi_p, wlo_p, n4w);
    }

    // Phase 1: input projection GEMM (tensor cores)
    dim3 gridA(G3H / 64, M_TOT / 128);
    cudaFuncSetAttribute(gemm_xgates_mma,
                         cudaFuncAttributeMaxDynamicSharedMemorySize, SMEM_GEMM);
    gemm_xgates_mma<<<gridA, 256, SMEM_GEMM>>>(b_ih);

    // Phase 2: persistent tensor-core recurrent scan
    cudaFuncSetAttribute(gru_scan_mma,
                         cudaFuncAttributeMaxDynamicSharedMemorySize, SMEM_SCAN);
    gru_scan_mma<<<NBLK, 256, SMEM_SCAN>>>(out, w_hh, b_hh);
}

// round 15
// speedup vs baseline: 8.2309x; 1.1264x over previous
#include <cuda_runtime.h>
#include <cuda_bf16.h>
#include <math.h>
#include <stdint.h>

// Problem constants
#define T_LEN 512
#define B_SZ  64
#define I_SZ  512
#define H_SZ  1024
#define G3H   3072
#define M_TOT 32768          // T*B

#define NBLK  128            // persistent blocks (1 per SM)
#define JT    8              // hidden units per block
#define NROW  24             // gate rows per block

// ---- scan smem (bytes) ----
#define WROWB   2064                        // W row stride (1024*2 + 16 pad)
#define WPL     (24 * WROWB)                // 49536 per plane (hi / lo)
#define OFF_A   (2 * WPL)                   // 99072
#define APL     768                         // A plane: 16 rows * 48B
#define WARPA   (3 * 2 * APL)               // 4608 per warp (3 buf x 2 planes)
#define OFF_RED (OFF_A + 16 * WARPA)        // 172800
#define REDW    26
#define SMEM_SCAN (OFF_RED + 4 * 64 * REDW * 4)   // 199424

// ---- gemm smem (bytes) ----
#define GA_PLANE (128 * 48)           // 6144
#define GB_PLANE (64 * 48)            // 3072
#define GBUF     (2 * GA_PLANE + 2 * GB_PLANE)   // 18432
#define SMEM_GEMM (2 * GBUF)          // 36864

typedef unsigned long long ull;
typedef unsigned short u16;

__device__ __align__(16) float g_gates[(size_t)M_TOT * G3H];
__device__ __align__(16) float g_h0[B_SZ * H_SZ];           // zeros, never written
__device__ __align__(16) u16 g_hhi[B_SZ * H_SZ];            // h bf16 hi
__device__ __align__(16) u16 g_hlo[B_SZ * H_SZ];            // h bf16 lo
__device__ __align__(16) u16 g_xhi[(size_t)M_TOT * I_SZ];   // x bf16 hi
__device__ __align__(16) u16 g_xlo[(size_t)M_TOT * I_SZ];   // x bf16 lo
__device__ __align__(16) u16 g_whi[(size_t)G3H * I_SZ];     // w_ih bf16 hi
__device__ __align__(16) u16 g_wlo[(size_t)G3H * I_SZ];     // w_ih bf16 lo
__device__ unsigned g_sync;

// ---------------------------------------------------------------------------
// helpers
// ---------------------------------------------------------------------------
__device__ __forceinline__ void mma16816(float* d, const unsigned* a,
                                         const unsigned* b) {
    asm volatile(
        "mma.sync.aligned.m16n8k16.row.col.f32.bf16.bf16.f32 "
        "{%0,%1,%2,%3}, {%4,%5,%6,%7}, {%8,%9}, {%0,%1,%2,%3};"
        : "+f"(d[0]), "+f"(d[1]), "+f"(d[2]), "+f"(d[3])
        : "r"(a[0]), "r"(a[1]), "r"(a[2]), "r"(a[3]), "r"(b[0]), "r"(b[1]));
}
__device__ __forceinline__ void ldmat4(unsigned* r, uint32_t addr) {
    asm volatile("ldmatrix.sync.aligned.m8n8.x4.shared.b16 {%0,%1,%2,%3}, [%4];"
                 : "=r"(r[0]), "=r"(r[1]), "=r"(r[2]), "=r"(r[3]) : "r"(addr));
}
__device__ __forceinline__ unsigned pack_bf2(float a, float b) {
    __nv_bfloat16 x = __float2bfloat16_rn(a);
    __nv_bfloat16 y = __float2bfloat16_rn(b);
    return (unsigned)__bfloat16_as_ushort(x)
         | ((unsigned)__bfloat16_as_ushort(y) << 16);
}
#define CP16(dst, src) \
    asm volatile("cp.async.cg.shared.global [%0], [%1], 16;" \
                 :: "r"(dst), "l"(src) : "memory")
#define CP_COMMIT() asm volatile("cp.async.commit_group;" ::: "memory")
#define CP_WAIT(n)  asm volatile("cp.async.wait_group %0;" :: "n"(n) : "memory")

// ---------------------------------------------------------------------------
// Conversion: f32 -> bf16 hi/lo
// ---------------------------------------------------------------------------
__global__ void cvt_hilo(const float* __restrict__ src,
                         u16* __restrict__ hi, u16* __restrict__ lo, int n4)
{
    int i = blockIdx.x * 256 + threadIdx.x;
    if (i >= n4) return;
    float4 v = ((const float4*)src)[i];
    unsigned h0 = pack_bf2(v.x, v.y);
    unsigned h1 = pack_bf2(v.z, v.w);
    float rx = v.x - __bfloat162float(__ushort_as_bfloat16((u16)h0));
    float ry = v.y - __bfloat162float(__ushort_as_bfloat16((u16)(h0 >> 16)));
    float rz = v.z - __bfloat162float(__ushort_as_bfloat16((u16)h1));
    float rw = v.w - __bfloat162float(__ushort_as_bfloat16((u16)(h1 >> 16)));
    ((uint2*)hi)[i] = make_uint2(h0, h1);
    ((uint2*)lo)[i] = make_uint2(pack_bf2(rx, ry), pack_bf2(rz, rw));
}

// ---------------------------------------------------------------------------
// Kernel A: x_gates = x @ w_ih^T + b_ih via mma.sync bf16 hi/lo (3-pass).
// (unchanged from round 14 — verified)
// ---------------------------------------------------------------------------
__global__ __launch_bounds__(256)
void gemm_xgates_mma(const float* __restrict__ bias)
{
    extern __shared__ __align__(16) char smem[];
    uint32_t sm32 = (uint32_t)__cvta_generic_to_shared((void*)smem);

    const int tid  = threadIdx.x;
    const int w    = tid >> 5;
    const int lane = tid & 31;
    const int wm   = w & 3;
    const int wn   = w >> 2;
    const int m0   = blockIdx.y * 128;
    const int n0   = blockIdx.x * 64;

    const int arow = tid >> 1, akh = tid & 1;
    const int bhl = tid >> 7, brem = tid & 127;
    const int brow = brem >> 1, bkh = brem & 1;

    float acc[2][4][4];
    #pragma unroll
    for (int mt = 0; mt < 2; mt++)
        #pragma unroll
        for (int nt = 0; nt < 4; nt++)
            #pragma unroll
            for (int i = 0; i < 4; i++) acc[mt][nt][i] = 0.f;

    auto stage = [&](int kt, int buf) {
        const int k0 = kt * 16;
        uint32_t bb = sm32 + (uint32_t)(buf * GBUF);
        uint32_t adst = bb + (uint32_t)(arow * 48 + akh * 16);
        const size_t asrc = (size_t)(m0 + arow) * I_SZ + k0 + akh * 8;
        CP16(adst,            g_xhi + asrc);
        CP16(adst + GA_PLANE, g_xlo + asrc);
        uint32_t bdst = bb + (uint32_t)(2 * GA_PLANE + bhl * GB_PLANE
                                        + brow * 48 + bkh * 16);
        const u16* bsrc = (bhl ? g_wlo : g_whi)
                        + (size_t)(n0 + brow) * I_SZ + k0 + bkh * 8;
        CP16(bdst, bsrc);
    };

    stage(0, 0);
    CP_COMMIT();

    const uint32_t lmA = (uint32_t)((wm * 32 + (lane & 15)) * 48
                                    + (lane >> 4) * 16);
    const int bnr = wn * 32 + (lane >> 2);
    const int bkl = (lane & 3) * 4;

    #pragma unroll 1
    for (int kt = 0; kt < 32; kt++) {
        const int buf = kt & 1;
        if (kt < 31) { stage(kt + 1, buf ^ 1); }
        CP_COMMIT();
        CP_WAIT(1);
        __syncthreads();

        uint32_t bb = sm32 + (uint32_t)(buf * GBUF);
        const char* bgen = smem + (size_t)buf * GBUF;

        unsigned Bh[4][2], Bl[4][2];
        #pragma unroll
        for (int nt = 0; nt < 4; nt++) {
            const char* p = bgen + 2 * GA_PLANE + (bnr + nt * 8) * 48 + bkl;
            Bh[nt][0] = *(const unsigned*)p;
            Bh[nt][1] = *(const unsigned*)(p + 16);
            Bl[nt][0] = *(const unsigned*)(p + GB_PLANE);
            Bl[nt][1] = *(const unsigned*)(p + GB_PLANE + 16);
        }
        #pragma unroll
        for (int mt = 0; mt < 2; mt++) {
            unsigned Ah[4], Al[4];
            ldmat4(Ah, bb + lmA + (uint32_t)(mt * 16 * 48));
            ldmat4(Al, bb + GA_PLANE + lmA + (uint32_t)(mt * 16 * 48));
            #pragma unroll
            for (int nt = 0; nt < 4; nt++) {
                mma16816(acc[mt][nt], Ah, Bh[nt]);
                mma16816(acc[mt][nt], Ah, Bl[nt]);
                mma16816(acc[mt][nt], Al, Bh[nt]);
            }
        }
        __syncthreads();
    }

    #pragma unroll
    for (int nt = 0; nt < 4; nt++) {
        int col = n0 + wn * 32 + nt * 8 + (lane & 3) * 2;
        float2 bv = *(const float2*)&bias[col];
        #pragma unroll
        for (int mt = 0; mt < 2; mt++) {
            int row = m0 + wm * 32 + mt * 16 + (lane >> 2);
            *(float2*)&g_gates[(size_t)row * G3H + col] =
                make_float2(acc[mt][nt][0] + bv.x, acc[mt][nt][1] + bv.y);
            *(float2*)&g_gates[(size_t)(row + 8) * G3H + col] =
                make_float2(acc[mt][nt][2] + bv.x, acc[mt][nt][3] + bv.y);
        }
    }
}

// ---------------------------------------------------------------------------
// Persistent GRU scan via mma.sync bf16 hi/lo — 16 warps, warp-private A.
// Warp (quad = w>>2, mt = w&3): k-slice [quad*256, +256), batches [mt*16,+16),
// all 24 gate rows.  W hi/lo resident in smem; per k-tile: 12 LDS.32 W-frags,
// 2 ldmatrix A (hi/lo), 9 HMMA.  Depth-3 warp-private cp.async A staging.
// ---------------------------------------------------------------------------
__global__ void __launch_bounds__(512, 1)
gru_scan_mma(float* __restrict__ out,
             const float* __restrict__ w_hh,
             const float* __restrict__ b_hh)
{
    extern __shared__ __align__(16) char smem[];
    uint32_t sm32 = (uint32_t)__cvta_generic_to_shared((void*)smem);
    float* Red = (float*)(smem + OFF_RED);

    const int tid  = threadIdx.x;
    const int w    = tid >> 5;
    const int lane = tid & 31;
    const int quad = w >> 2;              // k-slice index (0..3)
    const int mt   = w & 3;               // batch group (16 batches)
    const int j0   = blockIdx.x * JT;
    const int kofs = quad * 256;

    // ---- W -> smem bf16 hi/lo (once): rows 0..23 = g*8+jj ----
    for (int idx = tid; idx < NROW * (H_SZ / 4); idx += 512) {
        int row = idx >> 8;
        int q   = idx & 255;
        int g = row >> 3, jj = row & 7;
        float4 v = *(const float4*)&w_hh[(size_t)(g * H_SZ + j0 + jj) * H_SZ + 4 * q];
        u16* hi = (u16*)(smem + (size_t)row * WROWB + (size_t)q * 8);
        u16* lo = (u16*)(smem + WPL + (size_t)row * WROWB + (size_t)q * 8);
        float vv[4] = {v.x, v.y, v.z, v.w};
        #pragma unroll
        for (int e = 0; e < 4; e++) {
            __nv_bfloat16 bh = __float2bfloat16_rn(vv[e]);
            hi[e] = __bfloat16_as_ushort(bh);
            lo[e] = __bfloat16_as_ushort(
                __float2bfloat16_rn(vv[e] - __bfloat162float(bh)));
        }
    }

    // ---- epilogue mapping: one output per thread ----
    const int eb  = tid >> 3;
    const int ejj = tid & 7;
    const int ej  = j0 + ejj;
    const float bhr = b_hh[ej];
    const float bhz = b_hh[H_SZ + ej];
    const float bhn = b_hh[2 * H_SZ + ej];

    // ---- warp-private A staging mapping ----
    // chunk c in 0..63: plane = c>>5, row = (c&31)>>1, half = c&1
    const uint32_t abase = sm32 + (uint32_t)(OFF_A + w * WARPA);
    const uint32_t lmA   = (uint32_t)((lane & 15) * 48 + (lane >> 4) * 16);
    const int nl = lane >> 2;            // n within tile for W frags
    const int klb = (lane & 3) * 4;      // k byte offset (2 bf16)

    __syncthreads();

    unsigned target = NBLK;
    float* hn_out = out + (size_t)T_LEN * B_SZ * H_SZ;
    float hpv = 0.f;

    #pragma unroll 1
    for (int t = 0; t < T_LEN; t++) {
        const u16* hhi = (t == 0) ? (const u16*)g_h0 : g_hhi;
        const u16* hlo = (t == 0) ? (const u16*)g_h0 : g_hlo;
        float* ho = out + (size_t)t * B_SZ * H_SZ;

        // x-gate prefetch (overlaps mainloop)
        const float* xg = g_gates + (size_t)t * B_SZ * G3H
                        + (size_t)eb * G3H + ej;
        float xr = __ldcg(&xg[0]);
        float xz = __ldcg(&xg[H_SZ]);
        float xn = __ldcg(&xg[2 * H_SZ]);

        float acc[3][4];
        #pragma unroll
        for (int nt = 0; nt < 3; nt++)
            #pragma unroll
            for (int i = 0; i < 4; i++) acc[nt][i] = 0.f;

        // stage k-tile kt into buffer buf (warp-private, 2 CP16 per lane)
        auto stageA = [&](int kt, int buf) {
            const int ktk = kofs + kt * 16;
            uint32_t bb = abase + (uint32_t)(buf * 2 * APL);
            #pragma unroll
            for (int i = 0; i < 2; i++) {
                int c = lane + 32 * i;
                int plane = c >> 5;
                int row   = (c & 31) >> 1;
                int half  = c & 1;
                uint32_t dst = bb + (uint32_t)(plane * APL + row * 48 + half * 16);
                const u16* src = (plane ? hlo : hhi)
                               + (size_t)(mt * 16 + row) * H_SZ + ktk + half * 8;
                CP16(dst, src);
            }
            CP_COMMIT();
        };

        stageA(0, 0);
        stageA(1, 1);

        #pragma unroll 1
        for (int kt = 0; kt < 16; kt++) {
            const int buf = kt % 3;
            if (kt + 2 <= 15) stageA(kt + 2, (kt + 2) % 3);
            else              CP_COMMIT();
            CP_WAIT(2);
            __syncwarp();

            unsigned Ah[4], Al[4];
            uint32_t ab = abase + (uint32_t)(buf * 2 * APL) + lmA;
            ldmat4(Ah, ab);
            ldmat4(Al, ab + APL);

            const int kbyte = (kofs + kt * 16) * 2 + klb;
            #pragma unroll
            for (int nt = 0; nt < 3; nt++) {
                const char* pw = smem + (size_t)(nt * 8 + nl) * WROWB + kbyte;
                unsigned Bh[2], Bl[2];
                Bh[0] = *(const unsigned*)pw;
                Bh[1] = *(const unsigned*)(pw + 16);
                Bl[0] = *(const unsigned*)(pw + WPL);
                Bl[1] = *(const unsigned*)(pw + WPL + 16);
                mma16816(acc[nt], Ah, Bh);
                mma16816(acc[nt], Ah, Bl);
                mma16816(acc[nt], Al, Bh);
            }
        }

        // ---- D frags -> Red[quad][batch][row24] ----
        {
            float* Rw = Red + (size_t)quad * 64 * REDW;
            const int br = lane >> 2;
            const int cl = (lane & 3) * 2;
            #pragma unroll
            for (int nt = 0; nt < 3; nt++) {
                *(float2*)&Rw[(mt * 16 + br) * REDW + nt * 8 + cl] =
                    make_float2(acc[nt][0], acc[nt][1]);
                *(float2*)&Rw[(mt * 16 + br + 8) * REDW + nt * 8 + cl] =
                    make_float2(acc[nt][2], acc[nt][3]);
            }
        }
        __syncthreads();

        // ---- fused gate epilogue: 1 output per thread ----
        {
            float sr = 0.f, sz = 0.f, sn = 0.f;
            #pragma unroll
            for (int s = 0; s < 4; s++) {
                const float* R = Red + ((size_t)s * 64 + eb) * REDW;
                sr += R[ejj];
                sz += R[8 + ejj];
                sn += R[16 + ejj];
            }
            float r = 1.f / (1.f + expf(-(xr + sr + bhr)));
            float z = 1.f / (1.f + expf(-(xz + sz + bhz)));
            float n = tanhf(xn + r * (sn + bhn));
            float hnew = (1.f - z) * n + z * hpv;
            hpv = hnew;
            size_t oidx = (size_t)eb * H_SZ + ej;
            __stcg(&ho[oidx], hnew);
            if (t == T_LEN - 1) __stcg(&hn_out[oidx], hnew);
            __nv_bfloat16 bhh = __float2bfloat16_rn(hnew);
            float fh = __bfloat162float(bhh);
            __nv_bfloat16 bll = __float2bfloat16_rn(hnew - fh);
            g_hhi[oidx] = __bfloat16_as_ushort(bhh);
            g_hlo[oidx] = __bfloat16_as_ushort(bll);
        }

        // ---- grid-wide sync ----
        __threadfence();
        __syncthreads();
        if (tid == 0) {
            asm volatile("red.release.gpu.global.add.u32 [%0], %1;"
                         :: "l"(&g_sync), "r"(1u) : "memory");
            unsigned vv;
            do {
                asm volatile("ld.acquire.gpu.global.u32 %0, [%1];"
                             : "=r"(vv) : "l"(&g_sync) : "memory");
            } while (vv < target);
        }
        __syncthreads();
        target += NBLK;
    }
}

extern "C" void kernel_launch(void* const* d_in, const int* in_sizes, int n_in,
                              void* d_out, int out_size)
{
    const float* x    = (const float*)d_in[0];   // (T, B, I)
    const float* w_ih = (const float*)d_in[1];   // (3H, I)
    const float* w_hh = (const float*)d_in[2];   // (3H, H)
    const float* b_ih = (const float*)d_in[3];   // (3H,)
    const float* b_hh = (const float*)d_in[4];   // (3H,)
    float* out = (float*)d_out;

    // reset the grid-sync counter (graph-capturable H2D memcpy)
    static unsigned h_zero = 0;
    void* sync_addr = nullptr;
    cudaGetSymbolAddress(&sync_addr, g_sync);
    cudaMemcpyAsync(sync_addr, &h_zero, sizeof(unsigned),
                    cudaMemcpyHostToDevice, 0);

    // Phase 0: convert x and w_ih to bf16 hi/lo
    u16 *xhi_p, *xlo_p, *whi_p, *wlo_p;
    cudaGetSymbolAddress((void**)&xhi_p, g_xhi);
    cudaGetSymbolAddress((void**)&xlo_p, g_xlo);
    cudaGetSymbolAddress((void**)&whi_p, g_whi);
    cudaGetSymbolAddress((void**)&wlo_p, g_wlo);
    {
        int n4x = M_TOT * I_SZ / 4;
        cvt_hilo<<<(n4x + 255) / 256, 256>>>(x, xhi_p, xlo_p, n4x);
        int n4w = G3H * I_SZ / 4;
        cvt_hilo<<<(n4w + 255) / 256, 256>>>(w_ih, whi_p, wlo_p, n4w);
    }

    // Phase 1: input projection GEMM (tensor cores)
    dim3 gridA(G3H / 64, M_TOT / 128);
    cudaFuncSetAttribute(gemm_xgates_mma,
                         cudaFuncAttributeMaxDynamicSharedMemorySize, SMEM_GEMM);
    gemm_xgates_mma<<<gridA, 256, SMEM_GEMM>>>(b_ih);

    // Phase 2: persistent tensor-core recurrent scan
    cudaFuncSetAttribute(gru_scan_mma,
                         cudaFuncAttributeMaxDynamicSharedMemorySize, SMEM_SCAN);
    gru_scan_mma<<<NBLK, 512, SMEM_SCAN>>>(out, w_hh, b_hh);
}